// round 7
// baseline (speedup 1.0000x reference)
#include <cuda_runtime.h>
#include <math.h>

// ---------------------------------------------------------------------------
// Problem constants
// ---------------------------------------------------------------------------
constexpr int NU = 100000;
constexpr int NM = 20000;
constexpr int HD = 64;
constexpr int NE = 1000000;
constexpr int NEL = 500000;

typedef unsigned long long u64;

// ---------------------------------------------------------------------------
// Device scratch
// ---------------------------------------------------------------------------
__device__ __align__(16) float g_xu0[NU * HD];
__device__ __align__(16) float g_xm0[NM * HD];
__device__ __align__(16) float g_catu[NU * 3 * HD];
__device__ __align__(16) float g_catm[NM * 3 * HD];
__device__ __align__(16) float g_aggu[NU * HD];
__device__ __align__(16) float g_aggm[NM * HD];
__device__ __align__(16) float g_hu[NU * HD];
__device__ __align__(16) float g_hm[NM * HD];
__device__ __align__(16) float g_t1[(size_t)NEL * 64];
__device__ __align__(16) float g_t2[(size_t)NEL * 32];

__device__ int g_cntu[NU], g_cntm[NM];
__device__ int g_offu[NU + 1], g_offm[NM + 1];
__device__ int g_curu[NU], g_curm[NM];
__device__ int g_srcu[NE], g_srcm[NE];

__device__ float g_stats1[128], g_stats2[64];
__device__ float g_ab1[128], g_ab2[64];

// Transposed-weight scratch (all 10 GEMM weight sets, [col][k] layout)
//  off 0     : 3x um-layer  WT [64][128]  (Wl|Wr fused on k)
//  off 24576 : 3x mu-layer  WT [64][128]
//  off 49152 : JK-u         WT [64][192]
//  off 61440 : JK-m         WT [64][192]
//  off 73728 : classifier1  WT [64][128]
//  off 81920 : classifier2  WT [32][64]
constexpr int WT_UM = 0, WT_MU = 24576, WT_JKU = 49152, WT_JKM = 61440;
constexpr int WT_C1 = 73728, WT_C2 = 81920, WT_TOTAL = 83968;
__device__ __align__(16) float g_wt[WT_TOTAL];

// Per-GEMM weight slot (filled by cudaMemcpyAsync before each GEMM launch)
__constant__ __align__(16) float c_W[12288];   // up to 192*64 floats (48KB)

// ---------------------------------------------------------------------------
// Packed fp32-pair helpers, u64-native. fma.rn.f32x2 (arch>=1000) is
// bit-exact vs two scalar fp32 FMAs.
// ---------------------------------------------------------------------------
__device__ __forceinline__ u64 pk2(float lo, float hi) {
  u64 r; asm("mov.b64 %0, {%1, %2};" : "=l"(r) : "f"(lo), "f"(hi)); return r;
}
__device__ __forceinline__ u64 pkdup(float v) {
  u64 r; asm("mov.b64 %0, {%1, %1};" : "=l"(r) : "f"(v)); return r;
}
__device__ __forceinline__ void unpk2(u64 v, float& lo, float& hi) {
  asm("mov.b64 {%0, %1}, %2;" : "=f"(lo), "=f"(hi) : "l"(v));
}
__device__ __forceinline__ void ffma2(u64& acc, u64 a, u64 b) {
#if defined(__CUDA_ARCH__) && (__CUDA_ARCH__ >= 1000)
  asm("fma.rn.f32x2 %0, %1, %2, %0;" : "+l"(acc) : "l"(a), "l"(b));
#else
  float al, ah, bl, bh, cl, ch;
  unpk2(a, al, ah); unpk2(b, bl, bh); unpk2(acc, cl, ch);
  acc = pk2(fmaf(al, bl, cl), fmaf(ah, bh, ch));
#endif
}

// ---------------------------------------------------------------------------
// One-shot weight transposer: builds all WT sets in g_wt.
// ---------------------------------------------------------------------------
__global__ void k_wt(const float* __restrict__ Wl_um, const float* __restrict__ Wr_um,
                     const float* __restrict__ Wl_mu, const float* __restrict__ Wr_mu,
                     const float* __restrict__ puW, const float* __restrict__ pmW,
                     const float* __restrict__ W1, const float* __restrict__ W2) {
  int t = blockIdx.x * blockDim.x + threadIdx.x;
  if (t >= WT_TOTAL) return;
  float val;
  if (t < WT_MU) {                       // um layers
    int l = t / 8192, r = t % 8192, j = r / 128, k = r % 128;
    val = (k < 64) ? Wl_um[l * 4096 + k * 64 + j] : Wr_um[l * 4096 + (k - 64) * 64 + j];
  } else if (t < WT_JKU) {               // mu layers
    int r0 = t - WT_MU;
    int l = r0 / 8192, r = r0 % 8192, j = r / 128, k = r % 128;
    val = (k < 64) ? Wl_mu[l * 4096 + k * 64 + j] : Wr_mu[l * 4096 + (k - 64) * 64 + j];
  } else if (t < WT_JKM) {               // JK u
    int r = t - WT_JKU, j = r / 192, k = r % 192;
    val = puW[k * 64 + j];
  } else if (t < WT_C1) {                // JK m
    int r = t - WT_JKM, j = r / 192, k = r % 192;
    val = pmW[k * 64 + j];
  } else if (t < WT_C2) {                // classifier GEMM1
    int r = t - WT_C1, j = r / 128, k = r % 128;
    val = W1[k * 64 + j];
  } else {                               // classifier GEMM2
    int r = t - WT_C2, j = r / 64, k = r % 64;
    val = W2[k * 32 + j];
  }
  g_wt[t] = val;
}

// ---------------------------------------------------------------------------
// Init: gather x_u0 = user_emb[n_id], copy x_m0, zero counts + stats
// ---------------------------------------------------------------------------
__global__ void k_init(const int* __restrict__ n_id,
                       const float* __restrict__ user_emb,
                       const float* __restrict__ movie_x) {
  int t = blockIdx.x * blockDim.x + threadIdx.x;
  const int A = NU * 16, B = NM * 16, C = NU, D = NM;
  if (t < A) {
    int i = t >> 4, q = t & 15;
    ((float4*)g_xu0)[t] = ((const float4*)user_emb)[n_id[i] * 16 + q];
  } else if (t < A + B) {
    ((float4*)g_xm0)[t - A] = ((const float4*)movie_x)[t - A];
  } else if (t < A + B + C) {
    g_cntu[t - A - B] = 0;
  } else if (t < A + B + C + D) {
    g_cntm[t - A - B - C] = 0;
  } else {
    int j = t - (A + B + C + D);
    if (j < 128) g_stats1[j] = 0.f;
    else if (j < 192) g_stats2[j - 128] = 0.f;
  }
}

__global__ void k_count(const int* __restrict__ eu, const int* __restrict__ em) {
  int e = blockIdx.x * blockDim.x + threadIdx.x;
  if (e < NE) {
    atomicAdd(&g_cntu[eu[e]], 1);
    atomicAdd(&g_cntm[em[e]], 1);
  }
}

// Both scans in one launch: block 0 = users, block 1 = movies.
__global__ void k_scan2() {
  __shared__ int sp[1024];
  const int* cnt; int n; int* offs; int* cur;
  if (blockIdx.x == 0) { cnt = g_cntu; n = NU; offs = g_offu; cur = g_curu; }
  else                 { cnt = g_cntm; n = NM; offs = g_offm; cur = g_curm; }
  int t = threadIdx.x;
  int C = (n + 1023) >> 10;
  int b = t * C;
  int e = min(b + C, n);
  int s = 0;
  for (int i = b; i < e; i++) s += cnt[i];
  sp[t] = s;
  __syncthreads();
  for (int d = 1; d < 1024; d <<= 1) {
    int v = (t >= d) ? sp[t - d] : 0;
    __syncthreads();
    sp[t] += v;
    __syncthreads();
  }
  int pre = (t == 0) ? 0 : sp[t - 1];
  for (int i = b; i < e; i++) {
    offs[i] = pre; cur[i] = pre; pre += cnt[i];
  }
  if (b < n && e == n) offs[n] = pre;
}

__global__ void k_fill(const int* __restrict__ eu, const int* __restrict__ em) {
  int e = blockIdx.x * blockDim.x + threadIdx.x;
  if (e < NE) {
    int u = eu[e], m = em[e];
    g_srcm[atomicAdd(&g_curm[m], 1)] = u;
    g_srcu[atomicAdd(&g_curu[u], 1)] = m;
  }
}

// ---------------------------------------------------------------------------
// Mean aggregation: warp per dst; two half-warps, 4 neighbors in flight each.
// ---------------------------------------------------------------------------
__global__ void k_agg(const int* __restrict__ offs, const int* __restrict__ src,
                      const float* __restrict__ x, int ldx,
                      float* __restrict__ agg, int ndst) {
  int w = (blockIdx.x * blockDim.x + threadIdx.x) >> 5;
  if (w >= ndst) return;
  int lane = threadIdx.x & 31;
  int half = lane >> 4, li = lane & 15;
  int s0 = offs[w], s1 = offs[w + 1];
  float ax = 0.f, ay = 0.f, az = 0.f, aw = 0.f;
  int s = s0 + half;
  for (; s + 6 < s1; s += 8) {
    int ga = __ldg(src + s);
    int gb = __ldg(src + s + 2);
    int gc = __ldg(src + s + 4);
    int gd = __ldg(src + s + 6);
    float4 va = *(const float4*)(x + (size_t)ga * ldx + li * 4);
    float4 vb = *(const float4*)(x + (size_t)gb * ldx + li * 4);
    float4 vc = *(const float4*)(x + (size_t)gc * ldx + li * 4);
    float4 vd = *(const float4*)(x + (size_t)gd * ldx + li * 4);
    ax += va.x + vb.x + vc.x + vd.x;
    ay += va.y + vb.y + vc.y + vd.y;
    az += va.z + vb.z + vc.z + vd.z;
    aw += va.w + vb.w + vc.w + vd.w;
  }
  for (; s < s1; s += 2) {
    int g = __ldg(src + s);
    float4 v = *(const float4*)(x + (size_t)g * ldx + li * 4);
    ax += v.x; ay += v.y; az += v.z; aw += v.w;
  }
  ax += __shfl_xor_sync(0xffffffffu, ax, 16);
  ay += __shfl_xor_sync(0xffffffffu, ay, 16);
  az += __shfl_xor_sync(0xffffffffu, az, 16);
  aw += __shfl_xor_sync(0xffffffffu, aw, 16);
  if (half == 0) {
    float inv = 1.f / fmaxf((float)(s1 - s0), 1.f);
    *(float4*)(agg + (size_t)w * HD + li * 4) =
        make_float4(ax * inv, ay * inv, az * inv, aw * inv);
  }
}

// ---------------------------------------------------------------------------
// Gathered-row GEMM, 128-row x NOUT tile (64 rowpairs), 256 threads.
// A in smem (rowpair-packed u64, stride K+2); W read from __constant__ c_W
// (transposed [col][k]; half-warp-uniform LDC.128 -> broadcast).
// Smem = A only => 3 blocks/SM at K=128.
// ---------------------------------------------------------------------------
template <int K0, int K1, int NOUT, int MODE0, int RELU, int STATS>
__global__ __launch_bounds__(256) void k_gemm(
    const float* __restrict__ src0, int ld0, const int* __restrict__ gidx0,
    const float* __restrict__ src1, int ld1, const int* __restrict__ gidx1,
    const float* __restrict__ bias, const float* __restrict__ aff,
    float* __restrict__ out, int ldout, int nrows,
    float* __restrict__ stats) {
  constexpr int K = K0 + K1;
  constexpr int K4 = K / 4;
  constexpr int TN = NOUT / 16;
  constexpr int S8 = K + 2;       // u64 stride per rowpair
  constexpr size_t ASZ = (size_t)64 * S8 * 8;
  extern __shared__ __align__(16) char smem_raw[];
  u64* sA2 = (u64*)smem_raw;
  int* sidx = (int*)(smem_raw + ASZ);

  int tid = threadIdx.x;
  int rowBase = blockIdx.x * 128;

  // Preload gather indices (-1 => zero row)
  if (tid < 128) {
    int row = rowBase + tid;
    sidx[tid] = (row < nrows) ? (gidx0 ? gidx0[row] : row) : -1;
  } else if (K1 > 0) {
    int r = tid - 128;
    int row = rowBase + r;
    sidx[128 + r] = (row < nrows) ? (gidx1 ? gidx1[row] : row) : -1;
  }
  __syncthreads();

  // A tile: gather + pack 64 rowpairs x K4 float4-chunks
  for (int it = tid; it < 64 * K4; it += 256) {
    int rp = it & 63, k4 = it >> 6;
    int k = k4 * 4;
    float4 v0 = make_float4(0.f, 0.f, 0.f, 0.f);
    float4 v1 = make_float4(0.f, 0.f, 0.f, 0.f);
    if (k < K0) {
      int ga = sidx[2 * rp], gb = sidx[2 * rp + 1];
      if (ga >= 0) v0 = *(const float4*)(src0 + (size_t)ga * ld0 + k);
      if (gb >= 0) v1 = *(const float4*)(src0 + (size_t)gb * ld0 + k);
      if constexpr (MODE0 == 1) {  // BN affine + relu on input columns
        float a0 = aff[k], a1 = aff[k + 1], a2 = aff[k + 2], a3 = aff[k + 3];
        float c0 = aff[K0 + k], c1 = aff[K0 + k + 1], c2 = aff[K0 + k + 2], c3 = aff[K0 + k + 3];
        v0.x = fmaxf(a0 * v0.x + c0, 0.f); v0.y = fmaxf(a1 * v0.y + c1, 0.f);
        v0.z = fmaxf(a2 * v0.z + c2, 0.f); v0.w = fmaxf(a3 * v0.w + c3, 0.f);
        v1.x = fmaxf(a0 * v1.x + c0, 0.f); v1.y = fmaxf(a1 * v1.y + c1, 0.f);
        v1.z = fmaxf(a2 * v1.z + c2, 0.f); v1.w = fmaxf(a3 * v1.w + c3, 0.f);
      }
    } else {
      int ga = sidx[128 + 2 * rp], gb = sidx[128 + 2 * rp + 1];
      int kk = k - K0;
      if (ga >= 0) v0 = *(const float4*)(src1 + (size_t)ga * ld1 + kk);
      if (gb >= 0) v1 = *(const float4*)(src1 + (size_t)gb * ld1 + kk);
    }
    u64* dst = sA2 + (size_t)rp * S8 + k;
    *(ulonglong2*)dst = make_ulonglong2(pk2(v0.x, v1.x), pk2(v0.y, v1.y));
    *(ulonglong2*)(dst + 2) = make_ulonglong2(pk2(v0.z, v1.z), pk2(v0.w, v1.w));
  }
  __syncthreads();

  int lane = tid & 31;
  int tr = lane & 15;
  int tc = ((tid >> 5) << 1) | (lane >> 4);  // 0..15

  u64 acc[4][TN];
#pragma unroll
  for (int r = 0; r < 4; r++)
#pragma unroll
    for (int j = 0; j < TN; j++) acc[r][j] = 0ull;

#pragma unroll 4
  for (int k4 = 0; k4 < K4; k4++) {
    int k = k4 * 4;
    u64 a[4][4];
#pragma unroll
    for (int r = 0; r < 4; r++) {
      const ulonglong2* p = (const ulonglong2*)(sA2 + (size_t)(tr + r * 16) * S8 + k);
      ulonglong2 u = p[0];
      ulonglong2 v = p[1];
      a[r][0] = u.x; a[r][1] = u.y; a[r][2] = v.x; a[r][3] = v.y;
    }
#pragma unroll
    for (int j = 0; j < TN; j++) {
      float4 w4 = *(const float4*)(c_W + (size_t)(tc * TN + j) * K + k);  // LDC.128
      u64 w0 = pkdup(w4.x), w1 = pkdup(w4.y), w2 = pkdup(w4.z), w3 = pkdup(w4.w);
#pragma unroll
      for (int r = 0; r < 4; r++) {
        ffma2(acc[r][j], a[r][0], w0);
        ffma2(acc[r][j], a[r][1], w1);
        ffma2(acc[r][j], a[r][2], w2);
        ffma2(acc[r][j], a[r][3], w3);
      }
    }
  }

  // Bias into registers once
  float bcol[TN];
#pragma unroll
  for (int j = 0; j < TN; j++) bcol[j] = __ldg(bias + tc * TN + j);

  float ssum[TN], ssq[TN];
  if constexpr (STATS) {
#pragma unroll
    for (int j = 0; j < TN; j++) { ssum[j] = 0.f; ssq[j] = 0.f; }
  }

#pragma unroll
  for (int r = 0; r < 4; r++) {
    int rp = tr + r * 16;
    int row0 = rowBase + 2 * rp, row1 = row0 + 1;
    float v0[TN], v1[TN];
#pragma unroll
    for (int j = 0; j < TN; j++) {
      float lo, hi;
      unpk2(acc[r][j], lo, hi);
      lo += bcol[j]; hi += bcol[j];
      if constexpr (RELU) { lo = fmaxf(lo, 0.f); hi = fmaxf(hi, 0.f); }
      v0[j] = lo; v1[j] = hi;
      if constexpr (STATS) {
        if (row0 < nrows) { ssum[j] += lo; ssq[j] += lo * lo; }
        if (row1 < nrows) { ssum[j] += hi; ssq[j] += hi * hi; }
      }
    }
    if (row0 < nrows) {
      if constexpr (TN == 4)
        *(float4*)(out + (size_t)row0 * ldout + tc * 4) = make_float4(v0[0], v0[1], v0[2], v0[3]);
      else
        *(float2*)(out + (size_t)row0 * ldout + tc * 2) = make_float2(v0[0], v0[1]);
    }
    if (row1 < nrows) {
      if constexpr (TN == 4)
        *(float4*)(out + (size_t)row1 * ldout + tc * 4) = make_float4(v1[0], v1[1], v1[2], v1[3]);
      else
        *(float2*)(out + (size_t)row1 * ldout + tc * 2) = make_float2(v1[0], v1[1]);
    }
  }

  if constexpr (STATS) {
#pragma unroll
    for (int j = 0; j < TN; j++) {
      float s = ssum[j], q = ssq[j];
#pragma unroll
      for (int d = 8; d >= 1; d >>= 1) {
        s += __shfl_down_sync(0xffffffffu, s, d, 16);
        q += __shfl_down_sync(0xffffffffu, q, d, 16);
      }
      if (tr == 0) {
        int col = tc * TN + j;
        atomicAdd(&stats[col], s);
        atomicAdd(&stats[NOUT + col], q);
      }
    }
  }
}

// BN training-mode affine: a = g*rsqrt(var+eps), c = be - mean*a
__global__ void k_bnprep(const float* __restrict__ stats, const float* __restrict__ g,
                         const float* __restrict__ be, float* __restrict__ ab,
                         int n, float invN) {
  int j = threadIdx.x;
  if (j < n) {
    float m = stats[j] * invN;
    float v = stats[n + j] * invN - m * m;
    float a = g[j] * rsqrtf(v + 1e-5f);
    ab[j] = a;
    ab[n + j] = be[j] - m * a;
  }
}

// Final: out[e] = sum_j relu(a2[j]*t2[e][j]+c2[j]) * W3[j] + b3
__global__ void k_final(const float* __restrict__ W3, const float* __restrict__ b3,
                        float* __restrict__ out) {
  __shared__ float sa[32], sc[32], sw[32];
  int tid = threadIdx.x;
  if (tid < 32) { sa[tid] = g_ab2[tid]; sc[tid] = g_ab2[32 + tid]; sw[tid] = W3[tid]; }
  __syncthreads();
  int e = blockIdx.x * blockDim.x + tid;
  if (e < NEL) {
    const float4* r = (const float4*)(g_t2 + (size_t)e * 32);
    float acc = b3[0];
#pragma unroll
    for (int q = 0; q < 8; q++) {
      float4 v = r[q];
      int k = q * 4;
      acc += fmaxf(sa[k] * v.x + sc[k], 0.f) * sw[k];
      acc += fmaxf(sa[k + 1] * v.y + sc[k + 1], 0.f) * sw[k + 1];
      acc += fmaxf(sa[k + 2] * v.z + sc[k + 2], 0.f) * sw[k + 2];
      acc += fmaxf(sa[k + 3] * v.w + sc[k + 3], 0.f) * sw[k + 3];
    }
    out[e] = acc;
  }
}

// ---------------------------------------------------------------------------
// Host launcher
// ---------------------------------------------------------------------------
static inline int cdiv(int a, int b) { return (a + b - 1) / b; }
static inline int smemsz(int K) { return 64 * (K + 2) * 8 + 1024; }

extern "C" void kernel_launch(void* const* d_in, const int* in_sizes, int n_in,
                              void* d_out, int out_size) {
  const int*   n_id    = (const int*)d_in[0];
  const float* movie_x = (const float*)d_in[1];
  const int*   eu      = (const int*)d_in[2];
  const int*   em      = (const int*)d_in[3];
  const int*   lu      = (const int*)d_in[4];
  const int*   lm      = (const int*)d_in[5];
  const float* uemb    = (const float*)d_in[6];
  const float* Wl_um   = (const float*)d_in[7];
  const float* b_um    = (const float*)d_in[8];
  const float* Wr_um   = (const float*)d_in[9];
  const float* Wl_mu   = (const float*)d_in[10];
  const float* b_mu    = (const float*)d_in[11];
  const float* Wr_mu   = (const float*)d_in[12];
  const float* puW     = (const float*)d_in[13];
  const float* pub     = (const float*)d_in[14];
  const float* pmW     = (const float*)d_in[15];
  const float* pmb     = (const float*)d_in[16];
  const float* W1      = (const float*)d_in[17];
  const float* b1      = (const float*)d_in[18];
  const float* g1      = (const float*)d_in[19];
  const float* be1     = (const float*)d_in[20];
  const float* W2      = (const float*)d_in[21];
  const float* b2      = (const float*)d_in[22];
  const float* g2      = (const float*)d_in[23];
  const float* be2     = (const float*)d_in[24];
  const float* W3      = (const float*)d_in[25];
  const float* b3      = (const float*)d_in[26];
  float* out = (float*)d_out;

  float *xu0, *xm0, *catu, *catm, *aggu, *aggm, *hu, *hm, *t1, *t2;
  float *stats1, *stats2, *ab1, *ab2, *wt, *cw;
  int *offu, *offm, *srcu, *srcm;
  cudaGetSymbolAddress((void**)&xu0, g_xu0);
  cudaGetSymbolAddress((void**)&xm0, g_xm0);
  cudaGetSymbolAddress((void**)&catu, g_catu);
  cudaGetSymbolAddress((void**)&catm, g_catm);
  cudaGetSymbolAddress((void**)&aggu, g_aggu);
  cudaGetSymbolAddress((void**)&aggm, g_aggm);
  cudaGetSymbolAddress((void**)&hu, g_hu);
  cudaGetSymbolAddress((void**)&hm, g_hm);
  cudaGetSymbolAddress((void**)&t1, g_t1);
  cudaGetSymbolAddress((void**)&t2, g_t2);
  cudaGetSymbolAddress((void**)&stats1, g_stats1);
  cudaGetSymbolAddress((void**)&stats2, g_stats2);
  cudaGetSymbolAddress((void**)&ab1, g_ab1);
  cudaGetSymbolAddress((void**)&ab2, g_ab2);
  cudaGetSymbolAddress((void**)&offu, g_offu);
  cudaGetSymbolAddress((void**)&offm, g_offm);
  cudaGetSymbolAddress((void**)&srcu, g_srcu);
  cudaGetSymbolAddress((void**)&srcm, g_srcm);
  cudaGetSymbolAddress((void**)&wt, g_wt);
  cudaGetSymbolAddress((void**)&cw, c_W);

  const int SM128 = smemsz(128);   // 67584 B -> 3 blocks/SM
  const int SM192 = smemsz(192);   // 100352 B -> 2 blocks/SM
  const int SM64  = smemsz(64);    // 34816 B
  cudaFuncSetAttribute((const void*)k_gemm<64, 64, 64, 0, 1, 0>,
                       cudaFuncAttributeMaxDynamicSharedMemorySize, SM128);
  cudaFuncSetAttribute((const void*)k_gemm<64, 64, 64, 0, 0, 1>,
                       cudaFuncAttributeMaxDynamicSharedMemorySize, SM128);
  cudaFuncSetAttribute((const void*)k_gemm<192, 0, 64, 0, 0, 0>,
                       cudaFuncAttributeMaxDynamicSharedMemorySize, SM192);
  cudaFuncSetAttribute((const void*)k_gemm<64, 0, 32, 1, 0, 1>,
                       cudaFuncAttributeMaxDynamicSharedMemorySize, SM64);

  // --- launch 1: build all transposed weights ---
  k_wt<<<cdiv(WT_TOTAL, 256), 256>>>(Wl_um, Wr_um, Wl_mu, Wr_mu, puW, pmW, W1, W2);

  // --- launches 2-3: init + count ---
  int initThreads = NU * 16 + NM * 16 + NU + NM + 192;
  k_init<<<cdiv(initThreads, 256), 256>>>(n_id, uemb, movie_x);
  k_count<<<cdiv(NE, 256), 256>>>(eu, em);

  // --- launch 4 = ncu capture slot: PROFILING PROBE (classifier GEMM1 clone,
  // 32000 rows). Reads hu/hm (stale -> deterministic final output: stats go to
  // ab1, overwritten by k_bnprep; rows go to t1, overwritten by real GEMM1). ---
  cudaMemcpyAsync(cw, wt + WT_C1, 8192 * 4, cudaMemcpyDeviceToDevice);
  k_gemm<64, 64, 64, 0, 0, 1><<<cdiv(32000, 128), 256, SM128>>>(
      hu, 64, lu, hm, 64, lm, b1, nullptr, t1, 64, 32000, ab1);

  k_scan2<<<2, 1024>>>();
  k_fill<<<cdiv(NE, 256), 256>>>(eu, em);

  // --- 3 SAGE layers ---
  for (int l = 0; l < 3; l++) {
    const float* xu = l ? (catu + (l - 1) * 64) : xu0;
    const float* xm = l ? (catm + (l - 1) * 64) : xm0;
    int ldu = l ? 192 : 64;
    int ldm = l ? 192 : 64;

    k_agg<<<cdiv(NM * 32, 256), 256>>>(offm, srcm, xu, ldu, aggm, NM);
    k_agg<<<cdiv(NU * 32, 256), 256>>>(offu, srcu, xm, ldm, aggu, NU);

    cudaMemcpyAsync(cw, wt + WT_UM + l * 8192, 8192 * 4, cudaMemcpyDeviceToDevice);
    k_gemm<64, 64, 64, 0, 1, 0><<<cdiv(NM, 128), 256, SM128>>>(
        aggm, 64, nullptr, xm, ldm, nullptr, b_um + l * 64, nullptr,
        catm + l * 64, 192, NM, nullptr);
    cudaMemcpyAsync(cw, wt + WT_MU + l * 8192, 8192 * 4, cudaMemcpyDeviceToDevice);
    k_gemm<64, 64, 64, 0, 1, 0><<<cdiv(NU, 128), 256, SM128>>>(
        aggu, 64, nullptr, xu, ldu, nullptr, b_mu + l * 64, nullptr,
        catu + l * 64, 192, NU, nullptr);
  }

  // --- JK-cat projections ---
  cudaMemcpyAsync(cw, wt + WT_JKU, 12288 * 4, cudaMemcpyDeviceToDevice);
  k_gemm<192, 0, 64, 0, 0, 0><<<cdiv(NU, 128), 256, SM192>>>(
      catu, 192, nullptr, nullptr, 0, nullptr, pub, nullptr, hu, 64, NU, nullptr);
  cudaMemcpyAsync(cw, wt + WT_JKM, 12288 * 4, cudaMemcpyDeviceToDevice);
  k_gemm<192, 0, 64, 0, 0, 0><<<cdiv(NM, 128), 256, SM192>>>(
      catm, 192, nullptr, nullptr, 0, nullptr, pmb, nullptr, hm, 64, NM, nullptr);

  // --- classifier: t1 = [h_u[lu] | h_m[lm]] @ W1 + b1 (+ BN1 stats) ---
  cudaMemcpyAsync(cw, wt + WT_C1, 8192 * 4, cudaMemcpyDeviceToDevice);
  k_gemm<64, 64, 64, 0, 0, 1><<<cdiv(NEL, 128), 256, SM128>>>(
      hu, 64, lu, hm, 64, lm, b1, nullptr, t1, 64, NEL, stats1);
  k_bnprep<<<1, 64>>>(stats1, g1, be1, ab1, 64, 1.f / NEL);

  // --- t2 = relu(bn1(t1)) @ W2 + b2 (+ BN2 stats) ---
  cudaMemcpyAsync(cw, wt + WT_C2, 2048 * 4, cudaMemcpyDeviceToDevice);
  k_gemm<64, 0, 32, 1, 0, 1><<<cdiv(NEL, 128), 256, SM64>>>(
      t1, 64, nullptr, nullptr, 0, nullptr, b2, ab1, t2, 32, NEL, stats2);
  k_bnprep<<<1, 32>>>(stats2, g2, be2, ab2, 32, 1.f / NEL);

  // --- out = relu(bn2(t2)) @ W3 + b3 ---
  k_final<<<cdiv(NEL, 256), 256>>>(W3, b3, out);
}

// round 8
// speedup vs baseline: 3.5883x; 3.5883x over previous
#include <cuda_runtime.h>
#include <math.h>

// ---------------------------------------------------------------------------
// Problem constants
// ---------------------------------------------------------------------------
constexpr int NU = 100000;
constexpr int NM = 20000;
constexpr int HD = 64;
constexpr int NE = 1000000;
constexpr int NEL = 500000;

typedef unsigned long long u64;

// ---------------------------------------------------------------------------
// Device scratch
// ---------------------------------------------------------------------------
__device__ __align__(16) float g_xu0[NU * HD];
__device__ __align__(16) float g_xm0[NM * HD];
__device__ __align__(16) float g_catu[NU * 3 * HD];
__device__ __align__(16) float g_catm[NM * 3 * HD];
__device__ __align__(16) float g_aggu[NU * HD];
__device__ __align__(16) float g_aggm[NM * HD];
__device__ __align__(16) float g_hu[NU * HD];
__device__ __align__(16) float g_hm[NM * HD];
__device__ __align__(16) float g_t1[(size_t)NEL * 64];
__device__ __align__(16) float g_t2[(size_t)NEL * 32];

__device__ int g_cntu[NU], g_cntm[NM];
__device__ int g_offu[NU + 1], g_offm[NM + 1];
__device__ int g_curu[NU], g_curm[NM];
__device__ int g_srcu[NE], g_srcm[NE];

__device__ float g_stats1[128], g_stats2[64];
__device__ float g_ab1[128], g_ab2[64];

// Transposed-weight scratch (all 10 GEMM weight sets, [col][k] layout)
constexpr int WT_UM = 0, WT_MU = 24576, WT_JKU = 49152, WT_JKM = 61440;
constexpr int WT_C1 = 73728, WT_C2 = 81920, WT_TOTAL = 83968;
__device__ __align__(16) float g_wt[WT_TOTAL];

// ---------------------------------------------------------------------------
// Packed fp32-pair helpers, u64-native. fma.rn.f32x2 (arch>=1000) is
// bit-exact vs two scalar fp32 FMAs.
// ---------------------------------------------------------------------------
__device__ __forceinline__ u64 pk2(float lo, float hi) {
  u64 r; asm("mov.b64 %0, {%1, %2};" : "=l"(r) : "f"(lo), "f"(hi)); return r;
}
__device__ __forceinline__ u64 pkdup(float v) {
  u64 r; asm("mov.b64 %0, {%1, %1};" : "=l"(r) : "f"(v)); return r;
}
__device__ __forceinline__ void unpk2(u64 v, float& lo, float& hi) {
  asm("mov.b64 {%0, %1}, %2;" : "=f"(lo), "=f"(hi) : "l"(v));
}
__device__ __forceinline__ void ffma2(u64& acc, u64 a, u64 b) {
#if defined(__CUDA_ARCH__) && (__CUDA_ARCH__ >= 1000)
  asm("fma.rn.f32x2 %0, %1, %2, %0;" : "+l"(acc) : "l"(a), "l"(b));
#else
  float al, ah, bl, bh, cl, ch;
  unpk2(a, al, ah); unpk2(b, bl, bh); unpk2(acc, cl, ch);
  acc = pk2(fmaf(al, bl, cl), fmaf(ah, bh, ch));
#endif
}

// ---------------------------------------------------------------------------
// One-shot weight transposer: builds all WT sets in g_wt ([col][k] layout).
// ---------------------------------------------------------------------------
__global__ void k_wt(const float* __restrict__ Wl_um, const float* __restrict__ Wr_um,
                     const float* __restrict__ Wl_mu, const float* __restrict__ Wr_mu,
                     const float* __restrict__ puW, const float* __restrict__ pmW,
                     const float* __restrict__ W1, const float* __restrict__ W2) {
  int t = blockIdx.x * blockDim.x + threadIdx.x;
  if (t >= WT_TOTAL) return;
  float val;
  if (t < WT_MU) {                       // um layers: [64][128], Wl|Wr fused
    int l = t / 8192, r = t % 8192, j = r / 128, k = r % 128;
    val = (k < 64) ? Wl_um[l * 4096 + k * 64 + j] : Wr_um[l * 4096 + (k - 64) * 64 + j];
  } else if (t < WT_JKU) {               // mu layers
    int r0 = t - WT_MU;
    int l = r0 / 8192, r = r0 % 8192, j = r / 128, k = r % 128;
    val = (k < 64) ? Wl_mu[l * 4096 + k * 64 + j] : Wr_mu[l * 4096 + (k - 64) * 64 + j];
  } else if (t < WT_JKM) {               // JK u: [64][192]
    int r = t - WT_JKU, j = r / 192, k = r % 192;
    val = puW[k * 64 + j];
  } else if (t < WT_C1) {                // JK m
    int r = t - WT_JKM, j = r / 192, k = r % 192;
    val = pmW[k * 64 + j];
  } else if (t < WT_C2) {                // classifier GEMM1: [64][128]
    int r = t - WT_C1, j = r / 128, k = r % 128;
    val = W1[k * 64 + j];
  } else {                               // classifier GEMM2: [32][64]
    int r = t - WT_C2, j = r / 64, k = r % 64;
    val = W2[k * 32 + j];
  }
  g_wt[t] = val;
}

// ---------------------------------------------------------------------------
// Init: gather x_u0 = user_emb[n_id], copy x_m0, zero counts + stats
// ---------------------------------------------------------------------------
__global__ void k_init(const int* __restrict__ n_id,
                       const float* __restrict__ user_emb,
                       const float* __restrict__ movie_x) {
  int t = blockIdx.x * blockDim.x + threadIdx.x;
  const int A = NU * 16, B = NM * 16, C = NU, D = NM;
  if (t < A) {
    int i = t >> 4, q = t & 15;
    ((float4*)g_xu0)[t] = ((const float4*)user_emb)[n_id[i] * 16 + q];
  } else if (t < A + B) {
    ((float4*)g_xm0)[t - A] = ((const float4*)movie_x)[t - A];
  } else if (t < A + B + C) {
    g_cntu[t - A - B] = 0;
  } else if (t < A + B + C + D) {
    g_cntm[t - A - B - C] = 0;
  } else {
    int j = t - (A + B + C + D);
    if (j < 128) g_stats1[j] = 0.f;
    else if (j < 192) g_stats2[j - 128] = 0.f;
  }
}

__global__ void k_count(const int* __restrict__ eu, const int* __restrict__ em) {
  int e = blockIdx.x * blockDim.x + threadIdx.x;
  if (e < NE) {
    atomicAdd(&g_cntu[eu[e]], 1);
    atomicAdd(&g_cntm[em[e]], 1);
  }
}

// Both scans in one launch: block 0 = users, block 1 = movies.
__global__ void k_scan2() {
  __shared__ int sp[1024];
  const int* cnt; int n; int* offs; int* cur;
  if (blockIdx.x == 0) { cnt = g_cntu; n = NU; offs = g_offu; cur = g_curu; }
  else                 { cnt = g_cntm; n = NM; offs = g_offm; cur = g_curm; }
  int t = threadIdx.x;
  int C = (n + 1023) >> 10;
  int b = t * C;
  int e = min(b + C, n);
  int s = 0;
  for (int i = b; i < e; i++) s += cnt[i];
  sp[t] = s;
  __syncthreads();
  for (int d = 1; d < 1024; d <<= 1) {
    int v = (t >= d) ? sp[t - d] : 0;
    __syncthreads();
    sp[t] += v;
    __syncthreads();
  }
  int pre = (t == 0) ? 0 : sp[t - 1];
  for (int i = b; i < e; i++) {
    offs[i] = pre; cur[i] = pre; pre += cnt[i];
  }
  if (b < n && e == n) offs[n] = pre;
}

__global__ void k_fill(const int* __restrict__ eu, const int* __restrict__ em) {
  int e = blockIdx.x * blockDim.x + threadIdx.x;
  if (e < NE) {
    int u = eu[e], m = em[e];
    g_srcm[atomicAdd(&g_curm[m], 1)] = u;
    g_srcu[atomicAdd(&g_curu[u], 1)] = m;
  }
}

// ---------------------------------------------------------------------------
// Mean aggregation: warp per dst; two half-warps, 4 neighbors in flight each.
// ---------------------------------------------------------------------------
__global__ void k_agg(const int* __restrict__ offs, const int* __restrict__ src,
                      const float* __restrict__ x, int ldx,
                      float* __restrict__ agg, int ndst) {
  int w = (blockIdx.x * blockDim.x + threadIdx.x) >> 5;
  if (w >= ndst) return;
  int lane = threadIdx.x & 31;
  int half = lane >> 4, li = lane & 15;
  int s0 = offs[w], s1 = offs[w + 1];
  float ax = 0.f, ay = 0.f, az = 0.f, aw = 0.f;
  int s = s0 + half;
  for (; s + 6 < s1; s += 8) {
    int ga = __ldg(src + s);
    int gb = __ldg(src + s + 2);
    int gc = __ldg(src + s + 4);
    int gd = __ldg(src + s + 6);
    float4 va = *(const float4*)(x + (size_t)ga * ldx + li * 4);
    float4 vb = *(const float4*)(x + (size_t)gb * ldx + li * 4);
    float4 vc = *(const float4*)(x + (size_t)gc * ldx + li * 4);
    float4 vd = *(const float4*)(x + (size_t)gd * ldx + li * 4);
    ax += va.x + vb.x + vc.x + vd.x;
    ay += va.y + vb.y + vc.y + vd.y;
    az += va.z + vb.z + vc.z + vd.z;
    aw += va.w + vb.w + vc.w + vd.w;
  }
  for (; s < s1; s += 2) {
    int g = __ldg(src + s);
    float4 v = *(const float4*)(x + (size_t)g * ldx + li * 4);
    ax += v.x; ay += v.y; az += v.z; aw += v.w;
  }
  ax += __shfl_xor_sync(0xffffffffu, ax, 16);
  ay += __shfl_xor_sync(0xffffffffu, ay, 16);
  az += __shfl_xor_sync(0xffffffffu, az, 16);
  aw += __shfl_xor_sync(0xffffffffu, aw, 16);
  if (half == 0) {
    float inv = 1.f / fmaxf((float)(s1 - s0), 1.f);
    *(float4*)(agg + (size_t)w * HD + li * 4) =
        make_float4(ax * inv, ay * inv, az * inv, aw * inv);
  }
}

// ---------------------------------------------------------------------------
// Gathered-row GEMM, 128-row x NOUT tile (64 rowpairs), 256 threads.
// A in smem (rowpair-packed u64, stride K+2). W read via __ldg from the
// pre-transposed g_wt ([col][k]); W set is 32-48KB and L1-resident across
// k4 re-reads. Smem = A only => 3 blocks/SM at K=128.
// ---------------------------------------------------------------------------
template <int K0, int K1, int NOUT, int MODE0, int RELU, int STATS>
__global__ __launch_bounds__(256, 3) void k_gemm(
    const float* __restrict__ src0, int ld0, const int* __restrict__ gidx0,
    const float* __restrict__ src1, int ld1, const int* __restrict__ gidx1,
    const float* __restrict__ WT,
    const float* __restrict__ bias, const float* __restrict__ aff,
    float* __restrict__ out, int ldout, int nrows,
    float* __restrict__ stats) {
  constexpr int K = K0 + K1;
  constexpr int K4 = K / 4;
  constexpr int TN = NOUT / 16;
  constexpr int S8 = K + 2;       // u64 stride per rowpair
  constexpr size_t ASZ = (size_t)64 * S8 * 8;
  extern __shared__ __align__(16) char smem_raw[];
  u64* sA2 = (u64*)smem_raw;
  int* sidx = (int*)(smem_raw + ASZ);

  int tid = threadIdx.x;
  int rowBase = blockIdx.x * 128;

  // Preload gather indices (-1 => zero row)
  if (tid < 128) {
    int row = rowBase + tid;
    sidx[tid] = (row < nrows) ? (gidx0 ? gidx0[row] : row) : -1;
  } else if (K1 > 0) {
    int r = tid - 128;
    int row = rowBase + r;
    sidx[128 + r] = (row < nrows) ? (gidx1 ? gidx1[row] : row) : -1;
  }
  __syncthreads();

  // A tile: gather + pack 64 rowpairs x K4 float4-chunks
  for (int it = tid; it < 64 * K4; it += 256) {
    int rp = it & 63, k4 = it >> 6;
    int k = k4 * 4;
    float4 v0 = make_float4(0.f, 0.f, 0.f, 0.f);
    float4 v1 = make_float4(0.f, 0.f, 0.f, 0.f);
    if (k < K0) {
      int ga = sidx[2 * rp], gb = sidx[2 * rp + 1];
      if (ga >= 0) v0 = *(const float4*)(src0 + (size_t)ga * ld0 + k);
      if (gb >= 0) v1 = *(const float4*)(src0 + (size_t)gb * ld0 + k);
      if constexpr (MODE0 == 1) {  // BN affine + relu on input columns
        float a0 = aff[k], a1 = aff[k + 1], a2 = aff[k + 2], a3 = aff[k + 3];
        float c0 = aff[K0 + k], c1 = aff[K0 + k + 1], c2 = aff[K0 + k + 2], c3 = aff[K0 + k + 3];
        v0.x = fmaxf(a0 * v0.x + c0, 0.f); v0.y = fmaxf(a1 * v0.y + c1, 0.f);
        v0.z = fmaxf(a2 * v0.z + c2, 0.f); v0.w = fmaxf(a3 * v0.w + c3, 0.f);
        v1.x = fmaxf(a0 * v1.x + c0, 0.f); v1.y = fmaxf(a1 * v1.y + c1, 0.f);
        v1.z = fmaxf(a2 * v1.z + c2, 0.f); v1.w = fmaxf(a3 * v1.w + c3, 0.f);
      }
    } else {
      int ga = sidx[128 + 2 * rp], gb = sidx[128 + 2 * rp + 1];
      int kk = k - K0;
      if (ga >= 0) v0 = *(const float4*)(src1 + (size_t)ga * ld1 + kk);
      if (gb >= 0) v1 = *(const float4*)(src1 + (size_t)gb * ld1 + kk);
    }
    u64* dst = sA2 + (size_t)rp * S8 + k;
    *(ulonglong2*)dst = make_ulonglong2(pk2(v0.x, v1.x), pk2(v0.y, v1.y));
    *(ulonglong2*)(dst + 2) = make_ulonglong2(pk2(v0.z, v1.z), pk2(v0.w, v1.w));
  }
  __syncthreads();

  int lane = tid & 31;
  int tr = lane & 15;
  int tc = ((tid >> 5) << 1) | (lane >> 4);  // 0..15

  u64 acc[4][TN];
#pragma unroll
  for (int r = 0; r < 4; r++)
#pragma unroll
    for (int j = 0; j < TN; j++) acc[r][j] = 0ull;

#pragma unroll 4
  for (int k4 = 0; k4 < K4; k4++) {
    int k = k4 * 4;
    u64 a[4][4];
#pragma unroll
    for (int r = 0; r < 4; r++) {
      const ulonglong2* p = (const ulonglong2*)(sA2 + (size_t)(tr + r * 16) * S8 + k);
      ulonglong2 u = p[0];
      ulonglong2 v = p[1];
      a[r][0] = u.x; a[r][1] = u.y; a[r][2] = v.x; a[r][3] = v.y;
    }
#pragma unroll
    for (int j = 0; j < TN; j++) {
      float4 w4 = __ldg((const float4*)(WT + (size_t)(tc * TN + j) * K + k));  // L1-resident
      u64 w0 = pkdup(w4.x), w1 = pkdup(w4.y), w2 = pkdup(w4.z), w3 = pkdup(w4.w);
#pragma unroll
      for (int r = 0; r < 4; r++) {
        ffma2(acc[r][j], a[r][0], w0);
        ffma2(acc[r][j], a[r][1], w1);
        ffma2(acc[r][j], a[r][2], w2);
        ffma2(acc[r][j], a[r][3], w3);
      }
    }
  }

  // Bias into registers once
  float bcol[TN];
#pragma unroll
  for (int j = 0; j < TN; j++) bcol[j] = __ldg(bias + tc * TN + j);

  float ssum[TN], ssq[TN];
  if constexpr (STATS) {
#pragma unroll
    for (int j = 0; j < TN; j++) { ssum[j] = 0.f; ssq[j] = 0.f; }
  }

#pragma unroll
  for (int r = 0; r < 4; r++) {
    int rp = tr + r * 16;
    int row0 = rowBase + 2 * rp, row1 = row0 + 1;
    float v0[TN], v1[TN];
#pragma unroll
    for (int j = 0; j < TN; j++) {
      float lo, hi;
      unpk2(acc[r][j], lo, hi);
      lo += bcol[j]; hi += bcol[j];
      if constexpr (RELU) { lo = fmaxf(lo, 0.f); hi = fmaxf(hi, 0.f); }
      v0[j] = lo; v1[j] = hi;
      if constexpr (STATS) {
        if (row0 < nrows) { ssum[j] += lo; ssq[j] += lo * lo; }
        if (row1 < nrows) { ssum[j] += hi; ssq[j] += hi * hi; }
      }
    }
    if (row0 < nrows) {
      if constexpr (TN == 4)
        *(float4*)(out + (size_t)row0 * ldout + tc * 4) = make_float4(v0[0], v0[1], v0[2], v0[3]);
      else
        *(float2*)(out + (size_t)row0 * ldout + tc * 2) = make_float2(v0[0], v0[1]);
    }
    if (row1 < nrows) {
      if constexpr (TN == 4)
        *(float4*)(out + (size_t)row1 * ldout + tc * 4) = make_float4(v1[0], v1[1], v1[2], v1[3]);
      else
        *(float2*)(out + (size_t)row1 * ldout + tc * 2) = make_float2(v1[0], v1[1]);
    }
  }

  if constexpr (STATS) {
#pragma unroll
    for (int j = 0; j < TN; j++) {
      float s = ssum[j], q = ssq[j];
#pragma unroll
      for (int d = 8; d >= 1; d >>= 1) {
        s += __shfl_down_sync(0xffffffffu, s, d, 16);
        q += __shfl_down_sync(0xffffffffu, q, d, 16);
      }
      if (tr == 0) {
        int col = tc * TN + j;
        atomicAdd(&stats[col], s);
        atomicAdd(&stats[NOUT + col], q);
      }
    }
  }
}

// BN training-mode affine: a = g*rsqrt(var+eps), c = be - mean*a
__global__ void k_bnprep(const float* __restrict__ stats, const float* __restrict__ g,
                         const float* __restrict__ be, float* __restrict__ ab,
                         int n, float invN) {
  int j = threadIdx.x;
  if (j < n) {
    float m = stats[j] * invN;
    float v = stats[n + j] * invN - m * m;
    float a = g[j] * rsqrtf(v + 1e-5f);
    ab[j] = a;
    ab[n + j] = be[j] - m * a;
  }
}

// Final: out[e] = sum_j relu(a2[j]*t2[e][j]+c2[j]) * W3[j] + b3
__global__ void k_final(const float* __restrict__ W3, const float* __restrict__ b3,
                        float* __restrict__ out) {
  __shared__ float sa[32], sc[32], sw[32];
  int tid = threadIdx.x;
  if (tid < 32) { sa[tid] = g_ab2[tid]; sc[tid] = g_ab2[32 + tid]; sw[tid] = W3[tid]; }
  __syncthreads();
  int e = blockIdx.x * blockDim.x + tid;
  if (e < NEL) {
    const float4* r = (const float4*)(g_t2 + (size_t)e * 32);
    float acc = b3[0];
#pragma unroll
    for (int q = 0; q < 8; q++) {
      float4 v = r[q];
      int k = q * 4;
      acc += fmaxf(sa[k] * v.x + sc[k], 0.f) * sw[k];
      acc += fmaxf(sa[k + 1] * v.y + sc[k + 1], 0.f) * sw[k + 1];
      acc += fmaxf(sa[k + 2] * v.z + sc[k + 2], 0.f) * sw[k + 2];
      acc += fmaxf(sa[k + 3] * v.w + sc[k + 3], 0.f) * sw[k + 3];
    }
    out[e] = acc;
  }
}

// ---------------------------------------------------------------------------
// Host launcher
// ---------------------------------------------------------------------------
static inline int cdiv(int a, int b) { return (a + b - 1) / b; }
static inline int smemsz(int K) { return 64 * (K + 2) * 8 + 1024; }

extern "C" void kernel_launch(void* const* d_in, const int* in_sizes, int n_in,
                              void* d_out, int out_size) {
  const int*   n_id    = (const int*)d_in[0];
  const float* movie_x = (const float*)d_in[1];
  const int*   eu      = (const int*)d_in[2];
  const int*   em      = (const int*)d_in[3];
  const int*   lu      = (const int*)d_in[4];
  const int*   lm      = (const int*)d_in[5];
  const float* uemb    = (const float*)d_in[6];
  const float* Wl_um   = (const float*)d_in[7];
  const float* b_um    = (const float*)d_in[8];
  const float* Wr_um   = (const float*)d_in[9];
  const float* Wl_mu   = (const float*)d_in[10];
  const float* b_mu    = (const float*)d_in[11];
  const float* Wr_mu   = (const float*)d_in[12];
  const float* puW     = (const float*)d_in[13];
  const float* pub     = (const float*)d_in[14];
  const float* pmW     = (const float*)d_in[15];
  const float* pmb     = (const float*)d_in[16];
  const float* W1      = (const float*)d_in[17];
  const float* b1      = (const float*)d_in[18];
  const float* g1      = (const float*)d_in[19];
  const float* be1     = (const float*)d_in[20];
  const float* W2      = (const float*)d_in[21];
  const float* b2      = (const float*)d_in[22];
  const float* g2      = (const float*)d_in[23];
  const float* be2     = (const float*)d_in[24];
  const float* W3      = (const float*)d_in[25];
  const float* b3      = (const float*)d_in[26];
  float* out = (float*)d_out;

  float *xu0, *xm0, *catu, *catm, *aggu, *aggm, *hu, *hm, *t1, *t2;
  float *stats1, *stats2, *ab1, *ab2, *wt;
  int *offu, *offm, *srcu, *srcm;
  cudaGetSymbolAddress((void**)&xu0, g_xu0);
  cudaGetSymbolAddress((void**)&xm0, g_xm0);
  cudaGetSymbolAddress((void**)&catu, g_catu);
  cudaGetSymbolAddress((void**)&catm, g_catm);
  cudaGetSymbolAddress((void**)&aggu, g_aggu);
  cudaGetSymbolAddress((void**)&aggm, g_aggm);
  cudaGetSymbolAddress((void**)&hu, g_hu);
  cudaGetSymbolAddress((void**)&hm, g_hm);
  cudaGetSymbolAddress((void**)&t1, g_t1);
  cudaGetSymbolAddress((void**)&t2, g_t2);
  cudaGetSymbolAddress((void**)&stats1, g_stats1);
  cudaGetSymbolAddress((void**)&stats2, g_stats2);
  cudaGetSymbolAddress((void**)&ab1, g_ab1);
  cudaGetSymbolAddress((void**)&ab2, g_ab2);
  cudaGetSymbolAddress((void**)&offu, g_offu);
  cudaGetSymbolAddress((void**)&offm, g_offm);
  cudaGetSymbolAddress((void**)&srcu, g_srcu);
  cudaGetSymbolAddress((void**)&srcm, g_srcm);
  cudaGetSymbolAddress((void**)&wt, g_wt);

  const int SM128 = smemsz(128);   // 67584 B -> 3 blocks/SM
  const int SM192 = smemsz(192);   // 100352 B -> 2 blocks/SM
  const int SM64  = smemsz(64);    // 34816 B -> regs-limited 3
  cudaFuncSetAttribute((const void*)k_gemm<64, 64, 64, 0, 1, 0>,
                       cudaFuncAttributeMaxDynamicSharedMemorySize, SM128);
  cudaFuncSetAttribute((const void*)k_gemm<64, 64, 64, 0, 0, 1>,
                       cudaFuncAttributeMaxDynamicSharedMemorySize, SM128);
  cudaFuncSetAttribute((const void*)k_gemm<192, 0, 64, 0, 0, 0>,
                       cudaFuncAttributeMaxDynamicSharedMemorySize, SM192);
  cudaFuncSetAttribute((const void*)k_gemm<64, 0, 32, 1, 0, 1>,
                       cudaFuncAttributeMaxDynamicSharedMemorySize, SM64);

  // --- launch 1: build all transposed weights ---
  k_wt<<<cdiv(WT_TOTAL, 256), 256>>>(Wl_um, Wr_um, Wl_mu, Wr_mu, puW, pmW, W1, W2);

  // --- launches 2-3: init + count ---
  int initThreads = NU * 16 + NM * 16 + NU + NM + 192;
  k_init<<<cdiv(initThreads, 256), 256>>>(n_id, uemb, movie_x);
  k_count<<<cdiv(NE, 256), 256>>>(eu, em);

  // --- launch 4 = ncu capture slot: PROFILING PROBE (classifier GEMM1 clone,
  // 32000 rows; stats -> ab1 (overwritten by k_bnprep), rows -> t1
  // (overwritten by real GEMM1); reads stale hu/hm -> deterministic). ---
  k_gemm<64, 64, 64, 0, 0, 1><<<cdiv(32000, 128), 256, SM128>>>(
      hu, 64, lu, hm, 64, lm, wt + WT_C1, b1, nullptr, t1, 64, 32000, ab1);

  k_scan2<<<2, 1024>>>();
  k_fill<<<cdiv(NE, 256), 256>>>(eu, em);

  // --- 3 SAGE layers ---
  for (int l = 0; l < 3; l++) {
    const float* xu = l ? (catu + (l - 1) * 64) : xu0;
    const float* xm = l ? (catm + (l - 1) * 64) : xm0;
    int ldu = l ? 192 : 64;
    int ldm = l ? 192 : 64;

    k_agg<<<cdiv(NM * 32, 256), 256>>>(offm, srcm, xu, ldu, aggm, NM);
    k_agg<<<cdiv(NU * 32, 256), 256>>>(offu, srcu, xm, ldm, aggu, NU);

    k_gemm<64, 64, 64, 0, 1, 0><<<cdiv(NM, 128), 256, SM128>>>(
        aggm, 64, nullptr, xm, ldm, nullptr, wt + WT_UM + l * 8192,
        b_um + l * 64, nullptr, catm + l * 64, 192, NM, nullptr);
    k_gemm<64, 64, 64, 0, 1, 0><<<cdiv(NU, 128), 256, SM128>>>(
        aggu, 64, nullptr, xu, ldu, nullptr, wt + WT_MU + l * 8192,
        b_mu + l * 64, nullptr, catu + l * 64, 192, NU, nullptr);
  }

  // --- JK-cat projections ---
  k_gemm<192, 0, 64, 0, 0, 0><<<cdiv(NU, 128), 256, SM192>>>(
      catu, 192, nullptr, nullptr, 0, nullptr, wt + WT_JKU,
      pub, nullptr, hu, 64, NU, nullptr);
  k_gemm<192, 0, 64, 0, 0, 0><<<cdiv(NM, 128), 256, SM192>>>(
      catm, 192, nullptr, nullptr, 0, nullptr, wt + WT_JKM,
      pmb, nullptr, hm, 64, NM, nullptr);

  // --- classifier: t1 = [h_u[lu] | h_m[lm]] @ W1 + b1 (+ BN1 stats) ---
  k_gemm<64, 64, 64, 0, 0, 1><<<cdiv(NEL, 128), 256, SM128>>>(
      hu, 64, lu, hm, 64, lm, wt + WT_C1, b1, nullptr, t1, 64, NEL, stats1);
  k_bnprep<<<1, 64>>>(stats1, g1, be1, ab1, 64, 1.f / NEL);

  // --- t2 = relu(bn1(t1)) @ W2 + b2 (+ BN2 stats) ---
  k_gemm<64, 0, 32, 1, 0, 1><<<cdiv(NEL, 128), 256, SM64>>>(
      t1, 64, nullptr, nullptr, 0, nullptr, wt + WT_C2,
      b2, ab1, t2, 32, NEL, stats2);
  k_bnprep<<<1, 32>>>(stats2, g2, be2, ab2, 32, 1.f / NEL);

  // --- out = relu(bn2(t2)) @ W3 + b3 ---
  k_final<<<cdiv(NEL, 256), 256>>>(W3, b3, out);
}

// round 9
// speedup vs baseline: 3.7242x; 1.0379x over previous
#include <cuda_runtime.h>
#include <math.h>

// ---------------------------------------------------------------------------
// Problem constants
// ---------------------------------------------------------------------------
constexpr int NU = 100000;
constexpr int NM = 20000;
constexpr int HD = 64;
constexpr int NE = 1000000;
constexpr int NEL = 500000;

typedef unsigned long long u64;

// ---------------------------------------------------------------------------
// Device scratch
// ---------------------------------------------------------------------------
__device__ __align__(16) float g_xu0[NU * HD];
__device__ __align__(16) float g_xm0[NM * HD];
__device__ __align__(16) float g_catu[NU * 3 * HD];
__device__ __align__(16) float g_catm[NM * 3 * HD];
__device__ __align__(16) float g_aggu[NU * HD];
__device__ __align__(16) float g_aggm[NM * HD];
__device__ __align__(16) float g_hu[NU * HD];
__device__ __align__(16) float g_hm[NM * HD];
__device__ __align__(16) float g_t1[(size_t)NEL * 64];
__device__ __align__(16) float g_t2[(size_t)NEL * 32];

__device__ int g_cntu[NU], g_cntm[NM];
__device__ int g_offu[NU + 1], g_offm[NM + 1];
__device__ int g_curu[NU], g_curm[NM];
__device__ int g_srcu[NE], g_srcm[NE];

__device__ float g_stats1[128], g_stats2[64];
__device__ float g_ab1[128], g_ab2[64];

// Transposed-weight scratch (all GEMM weight sets, [col][k] layout)
constexpr int WT_UM = 0, WT_MU = 24576, WT_JKU = 49152, WT_JKM = 61440;
constexpr int WT_C1 = 73728, WT_C2 = 81920, WT_TOTAL = 83968;
__device__ __align__(16) float g_wt[WT_TOTAL];

// ---------------------------------------------------------------------------
// Packed fp32-pair helpers, u64-native. fma.rn.f32x2 (arch>=1000) is
// bit-exact vs two scalar fp32 FMAs.
// ---------------------------------------------------------------------------
__device__ __forceinline__ u64 pk2(float lo, float hi) {
  u64 r; asm("mov.b64 %0, {%1, %2};" : "=l"(r) : "f"(lo), "f"(hi)); return r;
}
__device__ __forceinline__ u64 pkdup(float v) {
  u64 r; asm("mov.b64 %0, {%1, %1};" : "=l"(r) : "f"(v)); return r;
}
__device__ __forceinline__ void unpk2(u64 v, float& lo, float& hi) {
  asm("mov.b64 {%0, %1}, %2;" : "=f"(lo), "=f"(hi) : "l"(v));
}
__device__ __forceinline__ void ffma2(u64& acc, u64 a, u64 b) {
#if defined(__CUDA_ARCH__) && (__CUDA_ARCH__ >= 1000)
  asm("fma.rn.f32x2 %0, %1, %2, %0;" : "+l"(acc) : "l"(a), "l"(b));
#else
  float al, ah, bl, bh, cl, ch;
  unpk2(a, al, ah); unpk2(b, bl, bh); unpk2(acc, cl, ch);
  acc = pk2(fmaf(al, bl, cl), fmaf(ah, bh, ch));
#endif
}

// ---------------------------------------------------------------------------
// One-shot weight transposer: builds all WT sets in g_wt ([col][k] layout).
// ---------------------------------------------------------------------------
__global__ void k_wt(const float* __restrict__ Wl_um, const float* __restrict__ Wr_um,
                     const float* __restrict__ Wl_mu, const float* __restrict__ Wr_mu,
                     const float* __restrict__ puW, const float* __restrict__ pmW,
                     const float* __restrict__ W1, const float* __restrict__ W2) {
  int t = blockIdx.x * blockDim.x + threadIdx.x;
  if (t >= WT_TOTAL) return;
  float val;
  if (t < WT_MU) {                       // um layers: [64][128], Wl|Wr fused
    int l = t / 8192, r = t % 8192, j = r / 128, k = r % 128;
    val = (k < 64) ? Wl_um[l * 4096 + k * 64 + j] : Wr_um[l * 4096 + (k - 64) * 64 + j];
  } else if (t < WT_JKU) {               // mu layers
    int r0 = t - WT_MU;
    int l = r0 / 8192, r = r0 % 8192, j = r / 128, k = r % 128;
    val = (k < 64) ? Wl_mu[l * 4096 + k * 64 + j] : Wr_mu[l * 4096 + (k - 64) * 64 + j];
  } else if (t < WT_JKM) {               // JK u: [64][192]
    int r = t - WT_JKU, j = r / 192, k = r % 192;
    val = puW[k * 64 + j];
  } else if (t < WT_C1) {                // JK m
    int r = t - WT_JKM, j = r / 192, k = r % 192;
    val = pmW[k * 64 + j];
  } else if (t < WT_C2) {                // classifier GEMM1: [64][128]
    int r = t - WT_C1, j = r / 128, k = r % 128;
    val = W1[k * 64 + j];
  } else {                               // classifier GEMM2: [32][64]
    int r = t - WT_C2, j = r / 64, k = r % 64;
    val = W2[k * 32 + j];
  }
  g_wt[t] = val;
}

// ---------------------------------------------------------------------------
// Init: gather x_u0 = user_emb[n_id], copy x_m0, zero counts + stats
// ---------------------------------------------------------------------------
__global__ void k_init(const int* __restrict__ n_id,
                       const float* __restrict__ user_emb,
                       const float* __restrict__ movie_x) {
  int t = blockIdx.x * blockDim.x + threadIdx.x;
  const int A = NU * 16, B = NM * 16, C = NU, D = NM;
  if (t < A) {
    int i = t >> 4, q = t & 15;
    ((float4*)g_xu0)[t] = ((const float4*)user_emb)[n_id[i] * 16 + q];
  } else if (t < A + B) {
    ((float4*)g_xm0)[t - A] = ((const float4*)movie_x)[t - A];
  } else if (t < A + B + C) {
    g_cntu[t - A - B] = 0;
  } else if (t < A + B + C + D) {
    g_cntm[t - A - B - C] = 0;
  } else {
    int j = t - (A + B + C + D);
    if (j < 128) g_stats1[j] = 0.f;
    else if (j < 192) g_stats2[j - 128] = 0.f;
  }
}

__global__ void k_count(const int* __restrict__ eu, const int* __restrict__ em) {
  int e = blockIdx.x * blockDim.x + threadIdx.x;
  if (e < NE) {
    atomicAdd(&g_cntu[eu[e]], 1);
    atomicAdd(&g_cntm[em[e]], 1);
  }
}

// Both scans in one launch: block 0 = users, block 1 = movies.
__global__ void k_scan2() {
  __shared__ int sp[1024];
  const int* cnt; int n; int* offs; int* cur;
  if (blockIdx.x == 0) { cnt = g_cntu; n = NU; offs = g_offu; cur = g_curu; }
  else                 { cnt = g_cntm; n = NM; offs = g_offm; cur = g_curm; }
  int t = threadIdx.x;
  int C = (n + 1023) >> 10;
  int b = t * C;
  int e = min(b + C, n);
  int s = 0;
  for (int i = b; i < e; i++) s += cnt[i];
  sp[t] = s;
  __syncthreads();
  for (int d = 1; d < 1024; d <<= 1) {
    int v = (t >= d) ? sp[t - d] : 0;
    __syncthreads();
    sp[t] += v;
    __syncthreads();
  }
  int pre = (t == 0) ? 0 : sp[t - 1];
  for (int i = b; i < e; i++) {
    offs[i] = pre; cur[i] = pre; pre += cnt[i];
  }
  if (b < n && e == n) offs[n] = pre;
}

__global__ void k_fill(const int* __restrict__ eu, const int* __restrict__ em) {
  int e = blockIdx.x * blockDim.x + threadIdx.x;
  if (e < NE) {
    int u = eu[e], m = em[e];
    g_srcm[atomicAdd(&g_curm[m], 1)] = u;
    g_srcu[atomicAdd(&g_curu[u], 1)] = m;
  }
}

// ---------------------------------------------------------------------------
// Mean aggregation core: warp per dst; two half-warps, 4 neighbors in flight.
// ---------------------------------------------------------------------------
__device__ __forceinline__ void agg_core(
    int w, int lane, const int* __restrict__ offs, const int* __restrict__ src,
    const float* __restrict__ x, int ldx, float* __restrict__ agg) {
  int half = lane >> 4, li = lane & 15;
  int s0 = offs[w], s1 = offs[w + 1];
  float ax = 0.f, ay = 0.f, az = 0.f, aw = 0.f;
  int s = s0 + half;
  for (; s + 6 < s1; s += 8) {
    int ga = __ldg(src + s);
    int gb = __ldg(src + s + 2);
    int gc = __ldg(src + s + 4);
    int gd = __ldg(src + s + 6);
    float4 va = *(const float4*)(x + (size_t)ga * ldx + li * 4);
    float4 vb = *(const float4*)(x + (size_t)gb * ldx + li * 4);
    float4 vc = *(const float4*)(x + (size_t)gc * ldx + li * 4);
    float4 vd = *(const float4*)(x + (size_t)gd * ldx + li * 4);
    ax += va.x + vb.x + vc.x + vd.x;
    ay += va.y + vb.y + vc.y + vd.y;
    az += va.z + vb.z + vc.z + vd.z;
    aw += va.w + vb.w + vc.w + vd.w;
  }
  for (; s < s1; s += 2) {
    int g = __ldg(src + s);
    float4 v = *(const float4*)(x + (size_t)g * ldx + li * 4);
    ax += v.x; ay += v.y; az += v.z; aw += v.w;
  }
  ax += __shfl_xor_sync(0xffffffffu, ax, 16);
  ay += __shfl_xor_sync(0xffffffffu, ay, 16);
  az += __shfl_xor_sync(0xffffffffu, az, 16);
  aw += __shfl_xor_sync(0xffffffffu, aw, 16);
  if (half == 0) {
    float inv = 1.f / fmaxf((float)(s1 - s0), 1.f);
    *(float4*)(agg + (size_t)w * HD + li * 4) =
        make_float4(ax * inv, ay * inv, az * inv, aw * inv);
  }
}

// Dual aggregation: warps [0,nA) -> problem A (movies), [nA,nA+nB) -> B (users)
__global__ void k_agg_dual(
    const int* __restrict__ offsA, const int* __restrict__ srcA,
    const float* __restrict__ xA, int ldA, float* __restrict__ aggA, int nA,
    const int* __restrict__ offsB, const int* __restrict__ srcB,
    const float* __restrict__ xB, int ldB, float* __restrict__ aggB, int nB) {
  int w = (blockIdx.x * blockDim.x + threadIdx.x) >> 5;
  int lane = threadIdx.x & 31;
  if (w < nA) agg_core(w, lane, offsA, srcA, xA, ldA, aggA);
  else if (w < nA + nB) agg_core(w - nA, lane, offsB, srcB, xB, ldB, aggB);
}

// ---------------------------------------------------------------------------
// Gathered-row GEMM core: 128-row x NOUT tile (64 rowpairs), 256 threads.
// A in smem (rowpair-packed u64, stride K+2). W via __ldg from pre-transposed
// [col][k] (L1-resident across k4 re-reads).
// ---------------------------------------------------------------------------
template <int K0, int K1, int NOUT, int MODE0, int RELU, int STATS>
__device__ __forceinline__ void gemm_core(
    int rowBase,
    const float* __restrict__ src0, int ld0, const int* __restrict__ gidx0,
    const float* __restrict__ src1, int ld1, const int* __restrict__ gidx1,
    const float* __restrict__ WT,
    const float* __restrict__ bias, const float* __restrict__ aff,
    float* __restrict__ out, int ldout, int nrows,
    float* __restrict__ stats, char* smem_raw) {
  constexpr int K = K0 + K1;
  constexpr int K4 = K / 4;
  constexpr int TN = NOUT / 16;
  constexpr int S8 = K + 2;       // u64 stride per rowpair
  constexpr size_t ASZ = (size_t)64 * S8 * 8;
  u64* sA2 = (u64*)smem_raw;
  int* sidx = (int*)(smem_raw + ASZ);

  int tid = threadIdx.x;

  // Preload gather indices (-1 => zero row)
  if (tid < 128) {
    int row = rowBase + tid;
    sidx[tid] = (row < nrows) ? (gidx0 ? gidx0[row] : row) : -1;
  } else if (K1 > 0) {
    int r = tid - 128;
    int row = rowBase + r;
    sidx[128 + r] = (row < nrows) ? (gidx1 ? gidx1[row] : row) : -1;
  }
  __syncthreads();

  // A tile: gather + pack 64 rowpairs x K4 float4-chunks
  for (int it = tid; it < 64 * K4; it += 256) {
    int rp = it & 63, k4 = it >> 6;
    int k = k4 * 4;
    float4 v0 = make_float4(0.f, 0.f, 0.f, 0.f);
    float4 v1 = make_float4(0.f, 0.f, 0.f, 0.f);
    if (k < K0) {
      int ga = sidx[2 * rp], gb = sidx[2 * rp + 1];
      if (ga >= 0) v0 = *(const float4*)(src0 + (size_t)ga * ld0 + k);
      if (gb >= 0) v1 = *(const float4*)(src0 + (size_t)gb * ld0 + k);
      if constexpr (MODE0 == 1) {  // BN affine + relu on input columns
        float a0 = aff[k], a1 = aff[k + 1], a2 = aff[k + 2], a3 = aff[k + 3];
        float c0 = aff[K0 + k], c1 = aff[K0 + k + 1], c2 = aff[K0 + k + 2], c3 = aff[K0 + k + 3];
        v0.x = fmaxf(a0 * v0.x + c0, 0.f); v0.y = fmaxf(a1 * v0.y + c1, 0.f);
        v0.z = fmaxf(a2 * v0.z + c2, 0.f); v0.w = fmaxf(a3 * v0.w + c3, 0.f);
        v1.x = fmaxf(a0 * v1.x + c0, 0.f); v1.y = fmaxf(a1 * v1.y + c1, 0.f);
        v1.z = fmaxf(a2 * v1.z + c2, 0.f); v1.w = fmaxf(a3 * v1.w + c3, 0.f);
      }
    } else {
      int ga = sidx[128 + 2 * rp], gb = sidx[128 + 2 * rp + 1];
      int kk = k - K0;
      if (ga >= 0) v0 = *(const float4*)(src1 + (size_t)ga * ld1 + kk);
      if (gb >= 0) v1 = *(const float4*)(src1 + (size_t)gb * ld1 + kk);
    }
    u64* dst = sA2 + (size_t)rp * S8 + k;
    *(ulonglong2*)dst = make_ulonglong2(pk2(v0.x, v1.x), pk2(v0.y, v1.y));
    *(ulonglong2*)(dst + 2) = make_ulonglong2(pk2(v0.z, v1.z), pk2(v0.w, v1.w));
  }
  __syncthreads();

  int lane = tid & 31;
  int tr = lane & 15;
  int tc = ((tid >> 5) << 1) | (lane >> 4);  // 0..15

  u64 acc[4][TN];
#pragma unroll
  for (int r = 0; r < 4; r++)
#pragma unroll
    for (int j = 0; j < TN; j++) acc[r][j] = 0ull;

#pragma unroll 4
  for (int k4 = 0; k4 < K4; k4++) {
    int k = k4 * 4;
    u64 a[4][4];
#pragma unroll
    for (int r = 0; r < 4; r++) {
      const ulonglong2* p = (const ulonglong2*)(sA2 + (size_t)(tr + r * 16) * S8 + k);
      ulonglong2 u = p[0];
      ulonglong2 v = p[1];
      a[r][0] = u.x; a[r][1] = u.y; a[r][2] = v.x; a[r][3] = v.y;
    }
#pragma unroll
    for (int j = 0; j < TN; j++) {
      float4 w4 = __ldg((const float4*)(WT + (size_t)(tc * TN + j) * K + k));
      u64 w0 = pkdup(w4.x), w1 = pkdup(w4.y), w2 = pkdup(w4.z), w3 = pkdup(w4.w);
#pragma unroll
      for (int r = 0; r < 4; r++) {
        ffma2(acc[r][j], a[r][0], w0);
        ffma2(acc[r][j], a[r][1], w1);
        ffma2(acc[r][j], a[r][2], w2);
        ffma2(acc[r][j], a[r][3], w3);
      }
    }
  }

  // Bias into registers once
  float bcol[TN];
#pragma unroll
  for (int j = 0; j < TN; j++) bcol[j] = __ldg(bias + tc * TN + j);

  float ssum[TN], ssq[TN];
  if constexpr (STATS) {
#pragma unroll
    for (int j = 0; j < TN; j++) { ssum[j] = 0.f; ssq[j] = 0.f; }
  }

#pragma unroll
  for (int r = 0; r < 4; r++) {
    int rp = tr + r * 16;
    int row0 = rowBase + 2 * rp, row1 = row0 + 1;
    float v0[TN], v1[TN];
#pragma unroll
    for (int j = 0; j < TN; j++) {
      float lo, hi;
      unpk2(acc[r][j], lo, hi);
      lo += bcol[j]; hi += bcol[j];
      if constexpr (RELU) { lo = fmaxf(lo, 0.f); hi = fmaxf(hi, 0.f); }
      v0[j] = lo; v1[j] = hi;
      if constexpr (STATS) {
        if (row0 < nrows) { ssum[j] += lo; ssq[j] += lo * lo; }
        if (row1 < nrows) { ssum[j] += hi; ssq[j] += hi * hi; }
      }
    }
    if (row0 < nrows) {
      if constexpr (TN == 4)
        *(float4*)(out + (size_t)row0 * ldout + tc * 4) = make_float4(v0[0], v0[1], v0[2], v0[3]);
      else
        *(float2*)(out + (size_t)row0 * ldout + tc * 2) = make_float2(v0[0], v0[1]);
    }
    if (row1 < nrows) {
      if constexpr (TN == 4)
        *(float4*)(out + (size_t)row1 * ldout + tc * 4) = make_float4(v1[0], v1[1], v1[2], v1[3]);
      else
        *(float2*)(out + (size_t)row1 * ldout + tc * 2) = make_float2(v1[0], v1[1]);
    }
  }

  if constexpr (STATS) {
#pragma unroll
    for (int j = 0; j < TN; j++) {
      float s = ssum[j], q = ssq[j];
#pragma unroll
      for (int d = 8; d >= 1; d >>= 1) {
        s += __shfl_down_sync(0xffffffffu, s, d, 16);
        q += __shfl_down_sync(0xffffffffu, q, d, 16);
      }
      if (tr == 0) {
        int col = tc * TN + j;
        atomicAdd(&stats[col], s);
        atomicAdd(&stats[NOUT + col], q);
      }
    }
  }
}

// Single-problem GEMM (classifier GEMM1/GEMM2: gather + stats + optional BN-in)
template <int K0, int K1, int NOUT, int MODE0, int RELU, int STATS>
__global__ __launch_bounds__(256, 3) void k_gemm(
    const float* __restrict__ src0, int ld0, const int* __restrict__ gidx0,
    const float* __restrict__ src1, int ld1, const int* __restrict__ gidx1,
    const float* __restrict__ WT,
    const float* __restrict__ bias, const float* __restrict__ aff,
    float* __restrict__ out, int ldout, int nrows,
    float* __restrict__ stats) {
  extern __shared__ __align__(16) char smem_raw[];
  gemm_core<K0, K1, NOUT, MODE0, RELU, STATS>(
      blockIdx.x * 128, src0, ld0, gidx0, src1, ld1, gidx1, WT, bias, aff,
      out, ldout, nrows, stats, smem_raw);
}

// Dual-problem GEMM (layer movie+user pair, or JK user+movie pair).
// Blocks [0,nb0) -> problem A, [nb0,...) -> problem B. No gather/stats/aff.
template <int K0, int K1, int NOUT, int RELU>
__global__ __launch_bounds__(256, 3) void k_gemm_dual(
    int nb0,
    const float* __restrict__ s0a, const float* __restrict__ s1a, int ld1a,
    const float* __restrict__ WTa, const float* __restrict__ biasa,
    float* __restrict__ outa, int nrowsa,
    const float* __restrict__ s0b, const float* __restrict__ s1b, int ld1b,
    const float* __restrict__ WTb, const float* __restrict__ biasb,
    float* __restrict__ outb, int nrowsb,
    int ld0, int ldout) {
  extern __shared__ __align__(16) char smem_raw[];
  if ((int)blockIdx.x < nb0)
    gemm_core<K0, K1, NOUT, 0, RELU, 0>(
        blockIdx.x * 128, s0a, ld0, nullptr, s1a, ld1a, nullptr, WTa, biasa,
        nullptr, outa, ldout, nrowsa, nullptr, smem_raw);
  else
    gemm_core<K0, K1, NOUT, 0, RELU, 0>(
        (blockIdx.x - nb0) * 128, s0b, ld0, nullptr, s1b, ld1b, nullptr, WTb,
        biasb, nullptr, outb, ldout, nrowsb, nullptr, smem_raw);
}

// BN training-mode affine: a = g*rsqrt(var+eps), c = be - mean*a
__global__ void k_bnprep(const float* __restrict__ stats, const float* __restrict__ g,
                         const float* __restrict__ be, float* __restrict__ ab,
                         int n, float invN) {
  int j = threadIdx.x;
  if (j < n) {
    float m = stats[j] * invN;
    float v = stats[n + j] * invN - m * m;
    float a = g[j] * rsqrtf(v + 1e-5f);
    ab[j] = a;
    ab[n + j] = be[j] - m * a;
  }
}

// Final: out[e] = sum_j relu(a2[j]*t2[e][j]+c2[j]) * W3[j] + b3
__global__ void k_final(const float* __restrict__ W3, const float* __restrict__ b3,
                        float* __restrict__ out) {
  __shared__ float sa[32], sc[32], sw[32];
  int tid = threadIdx.x;
  if (tid < 32) { sa[tid] = g_ab2[tid]; sc[tid] = g_ab2[32 + tid]; sw[tid] = W3[tid]; }
  __syncthreads();
  int e = blockIdx.x * blockDim.x + tid;
  if (e < NEL) {
    const float4* r = (const float4*)(g_t2 + (size_t)e * 32);
    float acc = b3[0];
#pragma unroll
    for (int q = 0; q < 8; q++) {
      float4 v = r[q];
      int k = q * 4;
      acc += fmaxf(sa[k] * v.x + sc[k], 0.f) * sw[k];
      acc += fmaxf(sa[k + 1] * v.y + sc[k + 1], 0.f) * sw[k + 1];
      acc += fmaxf(sa[k + 2] * v.z + sc[k + 2], 0.f) * sw[k + 2];
      acc += fmaxf(sa[k + 3] * v.w + sc[k + 3], 0.f) * sw[k + 3];
    }
    out[e] = acc;
  }
}

// ---------------------------------------------------------------------------
// Host launcher
// ---------------------------------------------------------------------------
static inline int cdiv(int a, int b) { return (a + b - 1) / b; }
static inline int smemsz(int K) { return 64 * (K + 2) * 8 + 1024; }

extern "C" void kernel_launch(void* const* d_in, const int* in_sizes, int n_in,
                              void* d_out, int out_size) {
  const int*   n_id    = (const int*)d_in[0];
  const float* movie_x = (const float*)d_in[1];
  const int*   eu      = (const int*)d_in[2];
  const int*   em      = (const int*)d_in[3];
  const int*   lu      = (const int*)d_in[4];
  const int*   lm      = (const int*)d_in[5];
  const float* uemb    = (const float*)d_in[6];
  const float* Wl_um   = (const float*)d_in[7];
  const float* b_um    = (const float*)d_in[8];
  const float* Wr_um   = (const float*)d_in[9];
  const float* Wl_mu   = (const float*)d_in[10];
  const float* b_mu    = (const float*)d_in[11];
  const float* Wr_mu   = (const float*)d_in[12];
  const float* puW     = (const float*)d_in[13];
  const float* pub     = (const float*)d_in[14];
  const float* pmW     = (const float*)d_in[15];
  const float* pmb     = (const float*)d_in[16];
  const float* W1      = (const float*)d_in[17];
  const float* b1      = (const float*)d_in[18];
  const float* g1      = (const float*)d_in[19];
  const float* be1     = (const float*)d_in[20];
  const float* W2      = (const float*)d_in[21];
  const float* b2      = (const float*)d_in[22];
  const float* g2      = (const float*)d_in[23];
  const float* be2     = (const float*)d_in[24];
  const float* W3      = (const float*)d_in[25];
  const float* b3      = (const float*)d_in[26];
  float* out = (float*)d_out;

  float *xu0, *xm0, *catu, *catm, *aggu, *aggm, *hu, *hm, *t1, *t2;
  float *stats1, *stats2, *ab1, *ab2, *wt;
  int *offu, *offm, *srcu, *srcm;
  cudaGetSymbolAddress((void**)&xu0, g_xu0);
  cudaGetSymbolAddress((void**)&xm0, g_xm0);
  cudaGetSymbolAddress((void**)&catu, g_catu);
  cudaGetSymbolAddress((void**)&catm, g_catm);
  cudaGetSymbolAddress((void**)&aggu, g_aggu);
  cudaGetSymbolAddress((void**)&aggm, g_aggm);
  cudaGetSymbolAddress((void**)&hu, g_hu);
  cudaGetSymbolAddress((void**)&hm, g_hm);
  cudaGetSymbolAddress((void**)&t1, g_t1);
  cudaGetSymbolAddress((void**)&t2, g_t2);
  cudaGetSymbolAddress((void**)&stats1, g_stats1);
  cudaGetSymbolAddress((void**)&stats2, g_stats2);
  cudaGetSymbolAddress((void**)&ab1, g_ab1);
  cudaGetSymbolAddress((void**)&ab2, g_ab2);
  cudaGetSymbolAddress((void**)&offu, g_offu);
  cudaGetSymbolAddress((void**)&offm, g_offm);
  cudaGetSymbolAddress((void**)&srcu, g_srcu);
  cudaGetSymbolAddress((void**)&srcm, g_srcm);
  cudaGetSymbolAddress((void**)&wt, g_wt);

  const int SM128 = smemsz(128);   // 67584 B -> 3 blocks/SM
  const int SM192 = smemsz(192);   // 100352 B -> 2 blocks/SM
  const int SM64  = smemsz(64);    // 34816 B
  cudaFuncSetAttribute((const void*)k_gemm<64, 64, 64, 0, 0, 1>,
                       cudaFuncAttributeMaxDynamicSharedMemorySize, SM128);
  cudaFuncSetAttribute((const void*)k_gemm<64, 0, 32, 1, 0, 1>,
                       cudaFuncAttributeMaxDynamicSharedMemorySize, SM64);
  cudaFuncSetAttribute((const void*)k_gemm_dual<64, 64, 64, 1>,
                       cudaFuncAttributeMaxDynamicSharedMemorySize, SM128);
  cudaFuncSetAttribute((const void*)k_gemm_dual<192, 0, 64, 0>,
                       cudaFuncAttributeMaxDynamicSharedMemorySize, SM192);

  // --- setup + CSR build ---
  k_wt<<<cdiv(WT_TOTAL, 256), 256>>>(Wl_um, Wr_um, Wl_mu, Wr_mu, puW, pmW, W1, W2);
  int initThreads = NU * 16 + NM * 16 + NU + NM + 192;
  k_init<<<cdiv(initThreads, 256), 256>>>(n_id, uemb, movie_x);
  k_count<<<cdiv(NE, 256), 256>>>(eu, em);
  k_scan2<<<2, 1024>>>();
  k_fill<<<cdiv(NE, 256), 256>>>(eu, em);

  const int NBM = cdiv(NM, 128);   // 157
  const int NBU = cdiv(NU, 128);   // 782
  const int AGG_BLOCKS = cdiv((NM + NU) * 32, 256);

  // --- 3 SAGE layers (agg + GEMM pairs merged per layer) ---
  for (int l = 0; l < 3; l++) {
    const float* xu = l ? (catu + (l - 1) * 64) : xu0;
    const float* xm = l ? (catm + (l - 1) * 64) : xm0;
    int ldu = l ? 192 : 64;
    int ldm = l ? 192 : 64;

    k_agg_dual<<<AGG_BLOCKS, 256>>>(
        offm, srcm, xu, ldu, aggm, NM,
        offu, srcu, xm, ldm, aggu, NU);

    k_gemm_dual<64, 64, 64, 1><<<NBM + NBU, 256, SM128>>>(
        NBM,
        aggm, xm, ldm, wt + WT_UM + l * 8192, b_um + l * 64, catm + l * 64, NM,
        aggu, xu, ldu, wt + WT_MU + l * 8192, b_mu + l * 64, catu + l * 64, NU,
        64, 192);
  }

  // --- JK-cat projections (merged) ---
  k_gemm_dual<192, 0, 64, 0><<<NBU + NBM, 256, SM192>>>(
      NBU,
      catu, nullptr, 0, wt + WT_JKU, pub, hu, NU,
      catm, nullptr, 0, wt + WT_JKM, pmb, hm, NM,
      192, 64);

  // --- classifier: t1 = [h_u[lu] | h_m[lm]] @ W1 + b1 (+ BN1 stats) ---
  k_gemm<64, 64, 64, 0, 0, 1><<<cdiv(NEL, 128), 256, SM128>>>(
      hu, 64, lu, hm, 64, lm, wt + WT_C1, b1, nullptr, t1, 64, NEL, stats1);
  k_bnprep<<<1, 64>>>(stats1, g1, be1, ab1, 64, 1.f / NEL);

  // --- t2 = relu(bn1(t1)) @ W2 + b2 (+ BN2 stats) ---
  k_gemm<64, 0, 32, 1, 0, 1><<<cdiv(NEL, 128), 256, SM64>>>(
      t1, 64, nullptr, nullptr, 0, nullptr, wt + WT_C2,
      b2, ab1, t2, 32, NEL, stats2);
  k_bnprep<<<1, 32>>>(stats2, g2, be2, ab2, 32, 1.f / NEL);

  // --- out = relu(bn2(t2)) @ W3 + b3 ---
  k_final<<<cdiv(NEL, 256), 256>>>(W3, b3, out);
}

// round 10
// speedup vs baseline: 4.2303x; 1.1359x over previous
#include <cuda_runtime.h>
#include <math.h>

// ---------------------------------------------------------------------------
// Problem constants
// ---------------------------------------------------------------------------
constexpr int NU = 100000;
constexpr int NM = 20000;
constexpr int HD = 64;
constexpr int NE = 1000000;
constexpr int NEL = 500000;

// Parallel-scan geometry: 4096 counts per block
constexpr int SC = 4096;
constexpr int BU = (NU + SC - 1) / SC;   // 25
constexpr int BM = (NM + SC - 1) / SC;   // 5
constexpr int NSB = BU + BM;             // 30

typedef unsigned long long u64;

// ---------------------------------------------------------------------------
// Device scratch
// ---------------------------------------------------------------------------
__device__ __align__(16) float g_xu0[NU * HD];
__device__ __align__(16) float g_xm0[NM * HD];
__device__ __align__(16) float g_catu[NU * 3 * HD];
__device__ __align__(16) float g_catm[NM * 3 * HD];
__device__ __align__(16) float g_aggu[NU * HD];
__device__ __align__(16) float g_aggm[NM * HD];
__device__ __align__(16) float g_hu[NU * HD];
__device__ __align__(16) float g_hm[NM * HD];
__device__ __align__(16) float g_t1[(size_t)NEL * 64];
__device__ __align__(16) float g_t2[(size_t)NEL * 32];

__device__ int g_cntu[NU], g_cntm[NM];
__device__ int g_offu[NU + 1], g_offm[NM + 1];
__device__ int g_curu[NU], g_curm[NM];
__device__ int g_srcu[NE], g_srcm[NE];
__device__ int g_part[NSB], g_part2[NSB];

__device__ float g_stats1[128], g_stats2[64];
__device__ float g_ab1[128], g_ab2[64];

// Transposed-weight scratch (all GEMM weight sets, [col][k] layout)
constexpr int WT_UM = 0, WT_MU = 24576, WT_JKU = 49152, WT_JKM = 61440;
constexpr int WT_C1 = 73728, WT_C2 = 81920, WT_TOTAL = 83968;
__device__ __align__(16) float g_wt[WT_TOTAL];

// ---------------------------------------------------------------------------
// Packed fp32-pair helpers, u64-native. fma.rn.f32x2 (arch>=1000) is
// bit-exact vs two scalar fp32 FMAs.
// ---------------------------------------------------------------------------
__device__ __forceinline__ u64 pk2(float lo, float hi) {
  u64 r; asm("mov.b64 %0, {%1, %2};" : "=l"(r) : "f"(lo), "f"(hi)); return r;
}
__device__ __forceinline__ u64 pkdup(float v) {
  u64 r; asm("mov.b64 %0, {%1, %1};" : "=l"(r) : "f"(v)); return r;
}
__device__ __forceinline__ void unpk2(u64 v, float& lo, float& hi) {
  asm("mov.b64 {%0, %1}, %2;" : "=f"(lo), "=f"(hi) : "l"(v));
}
__device__ __forceinline__ void ffma2(u64& acc, u64 a, u64 b) {
#if defined(__CUDA_ARCH__) && (__CUDA_ARCH__ >= 1000)
  asm("fma.rn.f32x2 %0, %1, %2, %0;" : "+l"(acc) : "l"(a), "l"(b));
#else
  float al, ah, bl, bh, cl, ch;
  unpk2(a, al, ah); unpk2(b, bl, bh); unpk2(acc, cl, ch);
  acc = pk2(fmaf(al, bl, cl), fmaf(ah, bh, ch));
#endif
}

// ---------------------------------------------------------------------------
// One-shot weight transposer: builds all WT sets in g_wt ([col][k] layout).
// ---------------------------------------------------------------------------
__global__ void k_wt(const float* __restrict__ Wl_um, const float* __restrict__ Wr_um,
                     const float* __restrict__ Wl_mu, const float* __restrict__ Wr_mu,
                     const float* __restrict__ puW, const float* __restrict__ pmW,
                     const float* __restrict__ W1, const float* __restrict__ W2) {
  int t = blockIdx.x * blockDim.x + threadIdx.x;
  if (t >= WT_TOTAL) return;
  float val;
  if (t < WT_MU) {                       // um layers: [64][128], Wl|Wr fused
    int l = t / 8192, r = t % 8192, j = r / 128, k = r % 128;
    val = (k < 64) ? Wl_um[l * 4096 + k * 64 + j] : Wr_um[l * 4096 + (k - 64) * 64 + j];
  } else if (t < WT_JKU) {               // mu layers
    int r0 = t - WT_MU;
    int l = r0 / 8192, r = r0 % 8192, j = r / 128, k = r % 128;
    val = (k < 64) ? Wl_mu[l * 4096 + k * 64 + j] : Wr_mu[l * 4096 + (k - 64) * 64 + j];
  } else if (t < WT_JKM) {               // JK u: [64][192]
    int r = t - WT_JKU, j = r / 192, k = r % 192;
    val = puW[k * 64 + j];
  } else if (t < WT_C1) {                // JK m
    int r = t - WT_JKM, j = r / 192, k = r % 192;
    val = pmW[k * 64 + j];
  } else if (t < WT_C2) {                // classifier GEMM1: [64][128]
    int r = t - WT_C1, j = r / 128, k = r % 128;
    val = W1[k * 64 + j];
  } else {                               // classifier GEMM2: [32][64]
    int r = t - WT_C2, j = r / 64, k = r % 64;
    val = W2[k * 32 + j];
  }
  g_wt[t] = val;
}

// ---------------------------------------------------------------------------
// Init: gather x_u0 = user_emb[n_id], copy x_m0, zero counts + stats
// ---------------------------------------------------------------------------
__global__ void k_init(const int* __restrict__ n_id,
                       const float* __restrict__ user_emb,
                       const float* __restrict__ movie_x) {
  int t = blockIdx.x * blockDim.x + threadIdx.x;
  const int A = NU * 16, B = NM * 16, C = NU, D = NM;
  if (t < A) {
    int i = t >> 4, q = t & 15;
    ((float4*)g_xu0)[t] = ((const float4*)user_emb)[n_id[i] * 16 + q];
  } else if (t < A + B) {
    ((float4*)g_xm0)[t - A] = ((const float4*)movie_x)[t - A];
  } else if (t < A + B + C) {
    g_cntu[t - A - B] = 0;
  } else if (t < A + B + C + D) {
    g_cntm[t - A - B - C] = 0;
  } else {
    int j = t - (A + B + C + D);
    if (j < 128) g_stats1[j] = 0.f;
    else if (j < 192) g_stats2[j - 128] = 0.f;
  }
}

__global__ void k_count(const int* __restrict__ eu, const int* __restrict__ em) {
  int e = blockIdx.x * blockDim.x + threadIdx.x;
  if (e < NE) {
    atomicAdd(&g_cntu[eu[e]], 1);
    atomicAdd(&g_cntm[em[e]], 1);
  }
}

// ---------------------------------------------------------------------------
// Parallel CSR scan, 3 phases. Blocks [0,BU) cover user counts, [BU,NSB)
// movie counts; each block owns SC=4096 counts.
// ---------------------------------------------------------------------------
__global__ void k_scan_a() {
  int b = blockIdx.x;
  const int* cnt; int n, bl;
  if (b < BU) { cnt = g_cntu; n = NU; bl = b; }
  else        { cnt = g_cntm; n = NM; bl = b - BU; }
  int i0 = bl * SC + threadIdx.x * 4;
  int s = 0;
#pragma unroll
  for (int j = 0; j < 4; j++) {
    int i = i0 + j;
    if (i < n) s += cnt[i];
  }
#pragma unroll
  for (int d = 16; d >= 1; d >>= 1) s += __shfl_down_sync(0xffffffffu, s, d);
  __shared__ int sp[32];
  int wid = threadIdx.x >> 5, lane = threadIdx.x & 31;
  if (lane == 0) sp[wid] = s;
  __syncthreads();
  if (wid == 0) {
    int v = sp[lane];
#pragma unroll
    for (int d = 16; d >= 1; d >>= 1) v += __shfl_down_sync(0xffffffffu, v, d);
    if (lane == 0) g_part[b] = v;
  }
}

__global__ void k_scan_b() {
  // single thread: exclusive bases over 30 partials, reset per segment
  int run = 0;
  for (int b = 0; b < BU; b++) { g_part2[b] = run; run += g_part[b]; }
  run = 0;
  for (int b = BU; b < NSB; b++) { g_part2[b] = run; run += g_part[b]; }
}

__global__ void k_scan_c() {
  int b = blockIdx.x;
  const int* cnt; int n, bl; int* offs; int* cur;
  if (b < BU) { cnt = g_cntu; n = NU; bl = b; offs = g_offu; cur = g_curu; }
  else        { cnt = g_cntm; n = NM; bl = b - BU; offs = g_offm; cur = g_curm; }
  int t = threadIdx.x;
  int i0 = bl * SC + t * 4;
  int v[4];
  int tsum = 0;
#pragma unroll
  for (int j = 0; j < 4; j++) {
    int i = i0 + j;
    v[j] = (i < n) ? cnt[i] : 0;
    tsum += v[j];
  }
  __shared__ int sp[1024];
  sp[t] = tsum;
  __syncthreads();
  for (int d = 1; d < 1024; d <<= 1) {
    int x = (t >= d) ? sp[t - d] : 0;
    __syncthreads();
    sp[t] += x;
    __syncthreads();
  }
  int p = g_part2[b] + sp[t] - tsum;   // exclusive prefix for element i0
#pragma unroll
  for (int j = 0; j < 4; j++) {
    int i = i0 + j;
    if (i < n) { offs[i] = p; cur[i] = p; p += v[j]; }
  }
  if (i0 <= n - 1 && n - 1 < i0 + 4) offs[n] = p;  // total for this segment
}

__global__ void k_fill(const int* __restrict__ eu, const int* __restrict__ em) {
  int e = blockIdx.x * blockDim.x + threadIdx.x;
  if (e < NE) {
    int u = eu[e], m = em[e];
    g_srcm[atomicAdd(&g_curm[m], 1)] = u;
    g_srcu[atomicAdd(&g_curu[u], 1)] = m;
  }
}

// ---------------------------------------------------------------------------
// Mean aggregation core: warp per dst; two half-warps, 4 neighbors in flight.
// ---------------------------------------------------------------------------
__device__ __forceinline__ void agg_core(
    int w, int lane, const int* __restrict__ offs, const int* __restrict__ src,
    const float* __restrict__ x, int ldx, float* __restrict__ agg) {
  int half = lane >> 4, li = lane & 15;
  int s0 = offs[w], s1 = offs[w + 1];
  float ax = 0.f, ay = 0.f, az = 0.f, aw = 0.f;
  int s = s0 + half;
  for (; s + 6 < s1; s += 8) {
    int ga = __ldg(src + s);
    int gb = __ldg(src + s + 2);
    int gc = __ldg(src + s + 4);
    int gd = __ldg(src + s + 6);
    float4 va = *(const float4*)(x + (size_t)ga * ldx + li * 4);
    float4 vb = *(const float4*)(x + (size_t)gb * ldx + li * 4);
    float4 vc = *(const float4*)(x + (size_t)gc * ldx + li * 4);
    float4 vd = *(const float4*)(x + (size_t)gd * ldx + li * 4);
    ax += va.x + vb.x + vc.x + vd.x;
    ay += va.y + vb.y + vc.y + vd.y;
    az += va.z + vb.z + vc.z + vd.z;
    aw += va.w + vb.w + vc.w + vd.w;
  }
  for (; s < s1; s += 2) {
    int g = __ldg(src + s);
    float4 v = *(const float4*)(x + (size_t)g * ldx + li * 4);
    ax += v.x; ay += v.y; az += v.z; aw += v.w;
  }
  ax += __shfl_xor_sync(0xffffffffu, ax, 16);
  ay += __shfl_xor_sync(0xffffffffu, ay, 16);
  az += __shfl_xor_sync(0xffffffffu, az, 16);
  aw += __shfl_xor_sync(0xffffffffu, aw, 16);
  if (half == 0) {
    float inv = 1.f / fmaxf((float)(s1 - s0), 1.f);
    *(float4*)(agg + (size_t)w * HD + li * 4) =
        make_float4(ax * inv, ay * inv, az * inv, aw * inv);
  }
}

// Dual aggregation: warps [0,nA) -> problem A (movies), [nA,nA+nB) -> B (users)
__global__ void k_agg_dual(
    const int* __restrict__ offsA, const int* __restrict__ srcA,
    const float* __restrict__ xA, int ldA, float* __restrict__ aggA, int nA,
    const int* __restrict__ offsB, const int* __restrict__ srcB,
    const float* __restrict__ xB, int ldB, float* __restrict__ aggB, int nB) {
  int w = (blockIdx.x * blockDim.x + threadIdx.x) >> 5;
  int lane = threadIdx.x & 31;
  if (w < nA) agg_core(w, lane, offsA, srcA, xA, ldA, aggA);
  else if (w < nA + nB) agg_core(w - nA, lane, offsB, srcB, xB, ldB, aggB);
}

// ---------------------------------------------------------------------------
// Gathered-row GEMM core: 128-row x NOUT tile (64 rowpairs), 256 threads.
// A in smem (rowpair-packed u64, stride K+2). W via __ldg from pre-transposed
// [col][k] (L1-resident across k4 re-reads).
// ---------------------------------------------------------------------------
template <int K0, int K1, int NOUT, int MODE0, int RELU, int STATS>
__device__ __forceinline__ void gemm_core(
    int rowBase,
    const float* __restrict__ src0, int ld0, const int* __restrict__ gidx0,
    const float* __restrict__ src1, int ld1, const int* __restrict__ gidx1,
    const float* __restrict__ WT,
    const float* __restrict__ bias, const float* __restrict__ aff,
    float* __restrict__ out, int ldout, int nrows,
    float* __restrict__ stats, char* smem_raw) {
  constexpr int K = K0 + K1;
  constexpr int K4 = K / 4;
  constexpr int TN = NOUT / 16;
  constexpr int S8 = K + 2;       // u64 stride per rowpair
  constexpr size_t ASZ = (size_t)64 * S8 * 8;
  u64* sA2 = (u64*)smem_raw;
  int* sidx = (int*)(smem_raw + ASZ);

  int tid = threadIdx.x;

  // Preload gather indices (-1 => zero row)
  if (tid < 128) {
    int row = rowBase + tid;
    sidx[tid] = (row < nrows) ? (gidx0 ? gidx0[row] : row) : -1;
  } else if (K1 > 0) {
    int r = tid - 128;
    int row = rowBase + r;
    sidx[128 + r] = (row < nrows) ? (gidx1 ? gidx1[row] : row) : -1;
  }
  __syncthreads();

  // A tile: gather + pack 64 rowpairs x K4 float4-chunks
  for (int it = tid; it < 64 * K4; it += 256) {
    int rp = it & 63, k4 = it >> 6;
    int k = k4 * 4;
    float4 v0 = make_float4(0.f, 0.f, 0.f, 0.f);
    float4 v1 = make_float4(0.f, 0.f, 0.f, 0.f);
    if (k < K0) {
      int ga = sidx[2 * rp], gb = sidx[2 * rp + 1];
      if (ga >= 0) v0 = *(const float4*)(src0 + (size_t)ga * ld0 + k);
      if (gb >= 0) v1 = *(const float4*)(src0 + (size_t)gb * ld0 + k);
      if constexpr (MODE0 == 1) {  // BN affine + relu on input columns
        float a0 = aff[k], a1 = aff[k + 1], a2 = aff[k + 2], a3 = aff[k + 3];
        float c0 = aff[K0 + k], c1 = aff[K0 + k + 1], c2 = aff[K0 + k + 2], c3 = aff[K0 + k + 3];
        v0.x = fmaxf(a0 * v0.x + c0, 0.f); v0.y = fmaxf(a1 * v0.y + c1, 0.f);
        v0.z = fmaxf(a2 * v0.z + c2, 0.f); v0.w = fmaxf(a3 * v0.w + c3, 0.f);
        v1.x = fmaxf(a0 * v1.x + c0, 0.f); v1.y = fmaxf(a1 * v1.y + c1, 0.f);
        v1.z = fmaxf(a2 * v1.z + c2, 0.f); v1.w = fmaxf(a3 * v1.w + c3, 0.f);
      }
    } else {
      int ga = sidx[128 + 2 * rp], gb = sidx[128 + 2 * rp + 1];
      int kk = k - K0;
      if (ga >= 0) v0 = *(const float4*)(src1 + (size_t)ga * ld1 + kk);
      if (gb >= 0) v1 = *(const float4*)(src1 + (size_t)gb * ld1 + kk);
    }
    u64* dst = sA2 + (size_t)rp * S8 + k;
    *(ulonglong2*)dst = make_ulonglong2(pk2(v0.x, v1.x), pk2(v0.y, v1.y));
    *(ulonglong2*)(dst + 2) = make_ulonglong2(pk2(v0.z, v1.z), pk2(v0.w, v1.w));
  }
  __syncthreads();

  int lane = tid & 31;
  int tr = lane & 15;
  int tc = ((tid >> 5) << 1) | (lane >> 4);  // 0..15

  u64 acc[4][TN];
#pragma unroll
  for (int r = 0; r < 4; r++)
#pragma unroll
    for (int j = 0; j < TN; j++) acc[r][j] = 0ull;

#pragma unroll 4
  for (int k4 = 0; k4 < K4; k4++) {
    int k = k4 * 4;
    u64 a[4][4];
#pragma unroll
    for (int r = 0; r < 4; r++) {
      const ulonglong2* p = (const ulonglong2*)(sA2 + (size_t)(tr + r * 16) * S8 + k);
      ulonglong2 u = p[0];
      ulonglong2 v = p[1];
      a[r][0] = u.x; a[r][1] = u.y; a[r][2] = v.x; a[r][3] = v.y;
    }
#pragma unroll
    for (int j = 0; j < TN; j++) {
      float4 w4 = __ldg((const float4*)(WT + (size_t)(tc * TN + j) * K + k));
      u64 w0 = pkdup(w4.x), w1 = pkdup(w4.y), w2 = pkdup(w4.z), w3 = pkdup(w4.w);
#pragma unroll
      for (int r = 0; r < 4; r++) {
        ffma2(acc[r][j], a[r][0], w0);
        ffma2(acc[r][j], a[r][1], w1);
        ffma2(acc[r][j], a[r][2], w2);
        ffma2(acc[r][j], a[r][3], w3);
      }
    }
  }

  // Bias into registers once
  float bcol[TN];
#pragma unroll
  for (int j = 0; j < TN; j++) bcol[j] = __ldg(bias + tc * TN + j);

  float ssum[TN], ssq[TN];
  if constexpr (STATS) {
#pragma unroll
    for (int j = 0; j < TN; j++) { ssum[j] = 0.f; ssq[j] = 0.f; }
  }

#pragma unroll
  for (int r = 0; r < 4; r++) {
    int rp = tr + r * 16;
    int row0 = rowBase + 2 * rp, row1 = row0 + 1;
    float v0[TN], v1[TN];
#pragma unroll
    for (int j = 0; j < TN; j++) {
      float lo, hi;
      unpk2(acc[r][j], lo, hi);
      lo += bcol[j]; hi += bcol[j];
      if constexpr (RELU) { lo = fmaxf(lo, 0.f); hi = fmaxf(hi, 0.f); }
      v0[j] = lo; v1[j] = hi;
      if constexpr (STATS) {
        if (row0 < nrows) { ssum[j] += lo; ssq[j] += lo * lo; }
        if (row1 < nrows) { ssum[j] += hi; ssq[j] += hi * hi; }
      }
    }
    if (row0 < nrows) {
      if constexpr (TN == 4)
        *(float4*)(out + (size_t)row0 * ldout + tc * 4) = make_float4(v0[0], v0[1], v0[2], v0[3]);
      else
        *(float2*)(out + (size_t)row0 * ldout + tc * 2) = make_float2(v0[0], v0[1]);
    }
    if (row1 < nrows) {
      if constexpr (TN == 4)
        *(float4*)(out + (size_t)row1 * ldout + tc * 4) = make_float4(v1[0], v1[1], v1[2], v1[3]);
      else
        *(float2*)(out + (size_t)row1 * ldout + tc * 2) = make_float2(v1[0], v1[1]);
    }
  }

  if constexpr (STATS) {
#pragma unroll
    for (int j = 0; j < TN; j++) {
      float s = ssum[j], q = ssq[j];
#pragma unroll
      for (int d = 8; d >= 1; d >>= 1) {
        s += __shfl_down_sync(0xffffffffu, s, d, 16);
        q += __shfl_down_sync(0xffffffffu, q, d, 16);
      }
      if (tr == 0) {
        int col = tc * TN + j;
        atomicAdd(&stats[col], s);
        atomicAdd(&stats[NOUT + col], q);
      }
    }
  }
}

// Single-problem GEMM (classifier GEMM1/GEMM2: gather + stats + optional BN-in)
template <int K0, int K1, int NOUT, int MODE0, int RELU, int STATS>
__global__ __launch_bounds__(256, 3) void k_gemm(
    const float* __restrict__ src0, int ld0, const int* __restrict__ gidx0,
    const float* __restrict__ src1, int ld1, const int* __restrict__ gidx1,
    const float* __restrict__ WT,
    const float* __restrict__ bias, const float* __restrict__ aff,
    float* __restrict__ out, int ldout, int nrows,
    float* __restrict__ stats) {
  extern __shared__ __align__(16) char smem_raw[];
  gemm_core<K0, K1, NOUT, MODE0, RELU, STATS>(
      blockIdx.x * 128, src0, ld0, gidx0, src1, ld1, gidx1, WT, bias, aff,
      out, ldout, nrows, stats, smem_raw);
}

// Dual-problem GEMM (layer movie+user pair, or JK user+movie pair).
// Blocks [0,nb0) -> problem A, [nb0,...) -> problem B. No gather/stats/aff.
template <int K0, int K1, int NOUT, int RELU>
__global__ __launch_bounds__(256, 3) void k_gemm_dual(
    int nb0,
    const float* __restrict__ s0a, const float* __restrict__ s1a, int ld1a,
    const float* __restrict__ WTa, const float* __restrict__ biasa,
    float* __restrict__ outa, int nrowsa,
    const float* __restrict__ s0b, const float* __restrict__ s1b, int ld1b,
    const float* __restrict__ WTb, const float* __restrict__ biasb,
    float* __restrict__ outb, int nrowsb,
    int ld0, int ldout) {
  extern __shared__ __align__(16) char smem_raw[];
  if ((int)blockIdx.x < nb0)
    gemm_core<K0, K1, NOUT, 0, RELU, 0>(
        blockIdx.x * 128, s0a, ld0, nullptr, s1a, ld1a, nullptr, WTa, biasa,
        nullptr, outa, ldout, nrowsa, nullptr, smem_raw);
  else
    gemm_core<K0, K1, NOUT, 0, RELU, 0>(
        (blockIdx.x - nb0) * 128, s0b, ld0, nullptr, s1b, ld1b, nullptr, WTb,
        biasb, nullptr, outb, ldout, nrowsb, nullptr, smem_raw);
}

// BN training-mode affine: a = g*rsqrt(var+eps), c = be - mean*a
__global__ void k_bnprep(const float* __restrict__ stats, const float* __restrict__ g,
                         const float* __restrict__ be, float* __restrict__ ab,
                         int n, float invN) {
  int j = threadIdx.x;
  if (j < n) {
    float m = stats[j] * invN;
    float v = stats[n + j] * invN - m * m;
    float a = g[j] * rsqrtf(v + 1e-5f);
    ab[j] = a;
    ab[n + j] = be[j] - m * a;
  }
}

// Final: out[e] = sum_j relu(a2[j]*t2[e][j]+c2[j]) * W3[j] + b3
__global__ void k_final(const float* __restrict__ W3, const float* __restrict__ b3,
                        float* __restrict__ out) {
  __shared__ float sa[32], sc[32], sw[32];
  int tid = threadIdx.x;
  if (tid < 32) { sa[tid] = g_ab2[tid]; sc[tid] = g_ab2[32 + tid]; sw[tid] = W3[tid]; }
  __syncthreads();
  int e = blockIdx.x * blockDim.x + tid;
  if (e < NEL) {
    const float4* r = (const float4*)(g_t2 + (size_t)e * 32);
    float acc = b3[0];
#pragma unroll
    for (int q = 0; q < 8; q++) {
      float4 v = r[q];
      int k = q * 4;
      acc += fmaxf(sa[k] * v.x + sc[k], 0.f) * sw[k];
      acc += fmaxf(sa[k + 1] * v.y + sc[k + 1], 0.f) * sw[k + 1];
      acc += fmaxf(sa[k + 2] * v.z + sc[k + 2], 0.f) * sw[k + 2];
      acc += fmaxf(sa[k + 3] * v.w + sc[k + 3], 0.f) * sw[k + 3];
    }
    out[e] = acc;
  }
}

// ---------------------------------------------------------------------------
// Host launcher
// ---------------------------------------------------------------------------
static inline int cdiv(int a, int b) { return (a + b - 1) / b; }
static inline int smemsz(int K) { return 64 * (K + 2) * 8 + 1024; }

extern "C" void kernel_launch(void* const* d_in, const int* in_sizes, int n_in,
                              void* d_out, int out_size) {
  const int*   n_id    = (const int*)d_in[0];
  const float* movie_x = (const float*)d_in[1];
  const int*   eu      = (const int*)d_in[2];
  const int*   em      = (const int*)d_in[3];
  const int*   lu      = (const int*)d_in[4];
  const int*   lm      = (const int*)d_in[5];
  const float* uemb    = (const float*)d_in[6];
  const float* Wl_um   = (const float*)d_in[7];
  const float* b_um    = (const float*)d_in[8];
  const float* Wr_um   = (const float*)d_in[9];
  const float* Wl_mu   = (const float*)d_in[10];
  const float* b_mu    = (const float*)d_in[11];
  const float* Wr_mu   = (const float*)d_in[12];
  const float* puW     = (const float*)d_in[13];
  const float* pub     = (const float*)d_in[14];
  const float* pmW     = (const float*)d_in[15];
  const float* pmb     = (const float*)d_in[16];
  const float* W1      = (const float*)d_in[17];
  const float* b1      = (const float*)d_in[18];
  const float* g1      = (const float*)d_in[19];
  const float* be1     = (const float*)d_in[20];
  const float* W2      = (const float*)d_in[21];
  const float* b2      = (const float*)d_in[22];
  const float* g2      = (const float*)d_in[23];
  const float* be2     = (const float*)d_in[24];
  const float* W3      = (const float*)d_in[25];
  const float* b3      = (const float*)d_in[26];
  float* out = (float*)d_out;

  float *xu0, *xm0, *catu, *catm, *aggu, *aggm, *hu, *hm, *t1, *t2;
  float *stats1, *stats2, *ab1, *ab2, *wt;
  int *offu, *offm, *srcu, *srcm;
  cudaGetSymbolAddress((void**)&xu0, g_xu0);
  cudaGetSymbolAddress((void**)&xm0, g_xm0);
  cudaGetSymbolAddress((void**)&catu, g_catu);
  cudaGetSymbolAddress((void**)&catm, g_catm);
  cudaGetSymbolAddress((void**)&aggu, g_aggu);
  cudaGetSymbolAddress((void**)&aggm, g_aggm);
  cudaGetSymbolAddress((void**)&hu, g_hu);
  cudaGetSymbolAddress((void**)&hm, g_hm);
  cudaGetSymbolAddress((void**)&t1, g_t1);
  cudaGetSymbolAddress((void**)&t2, g_t2);
  cudaGetSymbolAddress((void**)&stats1, g_stats1);
  cudaGetSymbolAddress((void**)&stats2, g_stats2);
  cudaGetSymbolAddress((void**)&ab1, g_ab1);
  cudaGetSymbolAddress((void**)&ab2, g_ab2);
  cudaGetSymbolAddress((void**)&offu, g_offu);
  cudaGetSymbolAddress((void**)&offm, g_offm);
  cudaGetSymbolAddress((void**)&srcu, g_srcu);
  cudaGetSymbolAddress((void**)&srcm, g_srcm);
  cudaGetSymbolAddress((void**)&wt, g_wt);

  const int SM128 = smemsz(128);   // 67584 B -> 3 blocks/SM
  const int SM192 = smemsz(192);   // 100352 B -> 2 blocks/SM
  const int SM64  = smemsz(64);    // 34816 B
  cudaFuncSetAttribute((const void*)k_gemm<64, 64, 64, 0, 0, 1>,
                       cudaFuncAttributeMaxDynamicSharedMemorySize, SM128);
  cudaFuncSetAttribute((const void*)k_gemm<64, 0, 32, 1, 0, 1>,
                       cudaFuncAttributeMaxDynamicSharedMemorySize, SM64);
  cudaFuncSetAttribute((const void*)k_gemm_dual<64, 64, 64, 1>,
                       cudaFuncAttributeMaxDynamicSharedMemorySize, SM128);
  cudaFuncSetAttribute((const void*)k_gemm_dual<192, 0, 64, 0>,
                       cudaFuncAttributeMaxDynamicSharedMemorySize, SM192);

  // --- setup + CSR build (parallel scan) ---
  k_wt<<<cdiv(WT_TOTAL, 256), 256>>>(Wl_um, Wr_um, Wl_mu, Wr_mu, puW, pmW, W1, W2);
  int initThreads = NU * 16 + NM * 16 + NU + NM + 192;
  k_init<<<cdiv(initThreads, 256), 256>>>(n_id, uemb, movie_x);
  k_count<<<cdiv(NE, 256), 256>>>(eu, em);
  k_scan_a<<<NSB, 1024>>>();
  k_scan_b<<<1, 1>>>();
  k_scan_c<<<NSB, 1024>>>();
  k_fill<<<cdiv(NE, 256), 256>>>(eu, em);

  const int NBM = cdiv(NM, 128);   // 157
  const int NBU = cdiv(NU, 128);   // 782
  const int AGG_BLOCKS = cdiv((NM + NU) * 32, 256);

  // --- 3 SAGE layers (agg + GEMM pairs merged per layer) ---
  for (int l = 0; l < 3; l++) {
    const float* xu = l ? (catu + (l - 1) * 64) : xu0;
    const float* xm = l ? (catm + (l - 1) * 64) : xm0;
    int ldu = l ? 192 : 64;
    int ldm = l ? 192 : 64;

    k_agg_dual<<<AGG_BLOCKS, 256>>>(
        offm, srcm, xu, ldu, aggm, NM,
        offu, srcu, xm, ldm, aggu, NU);

    k_gemm_dual<64, 64, 64, 1><<<NBM + NBU, 256, SM128>>>(
        NBM,
        aggm, xm, ldm, wt + WT_UM + l * 8192, b_um + l * 64, catm + l * 64, NM,
        aggu, xu, ldu, wt + WT_MU + l * 8192, b_mu + l * 64, catu + l * 64, NU,
        64, 192);
  }

  // --- JK-cat projections (merged) ---
  k_gemm_dual<192, 0, 64, 0><<<NBU + NBM, 256, SM192>>>(
      NBU,
      catu, nullptr, 0, wt + WT_JKU, pub, hu, NU,
      catm, nullptr, 0, wt + WT_JKM, pmb, hm, NM,
      192, 64);

  // --- classifier: t1 = [h_u[lu] | h_m[lm]] @ W1 + b1 (+ BN1 stats) ---
  k_gemm<64, 64, 64, 0, 0, 1><<<cdiv(NEL, 128), 256, SM128>>>(
      hu, 64, lu, hm, 64, lm, wt + WT_C1, b1, nullptr, t1, 64, NEL, stats1);
  k_bnprep<<<1, 64>>>(stats1, g1, be1, ab1, 64, 1.f / NEL);

  // --- t2 = relu(bn1(t1)) @ W2 + b2 (+ BN2 stats) ---
  k_gemm<64, 0, 32, 1, 0, 1><<<cdiv(NEL, 128), 256, SM64>>>(
      t1, 64, nullptr, nullptr, 0, nullptr, wt + WT_C2,
      b2, ab1, t2, 32, NEL, stats2);
  k_bnprep<<<1, 32>>>(stats2, g2, be2, ab2, 32, 1.f / NEL);

  // --- out = relu(bn2(t2)) @ W3 + b3 ---
  k_final<<<cdiv(NEL, 256), 256>>>(W3, b3, out);
}

// round 11
// speedup vs baseline: 5.5450x; 1.3108x over previous
#include <cuda_runtime.h>
#include <math.h>

// ---------------------------------------------------------------------------
// Problem constants
// ---------------------------------------------------------------------------
constexpr int NU = 100000;
constexpr int NM = 20000;
constexpr int HD = 64;
constexpr int NE = 1000000;
constexpr int NEL = 500000;

// Parallel-scan geometry: 4096 counts per block
constexpr int SC = 4096;
constexpr int BU = (NU + SC - 1) / SC;   // 25
constexpr int BM = (NM + SC - 1) / SC;   // 5
constexpr int NSB = BU + BM;             // 30

typedef unsigned long long u64;

// ---------------------------------------------------------------------------
// Device scratch
// ---------------------------------------------------------------------------
__device__ __align__(16) float g_xu0[NU * HD];
__device__ __align__(16) float g_xm0[NM * HD];
__device__ __align__(16) float g_catu[NU * 3 * HD];
__device__ __align__(16) float g_catm[NM * 3 * HD];
__device__ __align__(16) float g_aggu[NU * HD];
__device__ __align__(16) float g_aggm[NM * HD];
__device__ __align__(16) float g_hu[NU * HD];     // now holds pu = catu@Wcu+bu'
__device__ __align__(16) float g_hm[NM * HD];     // now holds pm = catm@Wcm+bm'
__device__ __align__(16) float g_t1[(size_t)NEL * 64];
__device__ __align__(16) float g_t2[(size_t)NEL * 32];

__device__ int g_cntu[NU], g_cntm[NM];
__device__ int g_offu[NU + 1], g_offm[NM + 1];
__device__ int g_curu[NU], g_curm[NM];
__device__ int g_srcu[NE], g_srcm[NE];
__device__ int g_part[NSB], g_part2[NSB];

__device__ float g_stats1[128], g_stats2[64];
__device__ float g_ab1[128], g_ab2[64];
__device__ float g_cbias[128];   // [bu'+b1 | bm'] composed classifier biases

// Transposed-weight scratch ([col][k] layout)
constexpr int WT_UM = 0, WT_MU = 24576, WT_JKU = 49152, WT_JKM = 61440;
constexpr int WT_C1 = 73728, WT_C2 = 81920, WT_TOTAL = 83968;
__device__ __align__(16) float g_wt[WT_TOTAL];

// ---------------------------------------------------------------------------
// Packed fp32-pair helpers, u64-native. fma.rn.f32x2 (arch>=1000) is
// bit-exact vs two scalar fp32 FMAs.
// ---------------------------------------------------------------------------
__device__ __forceinline__ u64 pk2(float lo, float hi) {
  u64 r; asm("mov.b64 %0, {%1, %2};" : "=l"(r) : "f"(lo), "f"(hi)); return r;
}
__device__ __forceinline__ u64 pkdup(float v) {
  u64 r; asm("mov.b64 %0, {%1, %1};" : "=l"(r) : "f"(v)); return r;
}
__device__ __forceinline__ void unpk2(u64 v, float& lo, float& hi) {
  asm("mov.b64 {%0, %1}, %2;" : "=f"(lo), "=f"(hi) : "l"(v));
}
__device__ __forceinline__ void ffma2(u64& acc, u64 a, u64 b) {
#if defined(__CUDA_ARCH__) && (__CUDA_ARCH__ >= 1000)
  asm("fma.rn.f32x2 %0, %1, %2, %0;" : "+l"(acc) : "l"(a), "l"(b));
#else
  float al, ah, bl, bh, cl, ch;
  unpk2(a, al, ah); unpk2(b, bl, bh); unpk2(acc, cl, ch);
  acc = pk2(fmaf(al, bl, cl), fmaf(ah, bh, ch));
#endif
}

// ---------------------------------------------------------------------------
// One-shot weight transposer (layer weights + classifier GEMM2).
// ---------------------------------------------------------------------------
__global__ void k_wt(const float* __restrict__ Wl_um, const float* __restrict__ Wr_um,
                     const float* __restrict__ Wl_mu, const float* __restrict__ Wr_mu,
                     const float* __restrict__ W2) {
  int t = blockIdx.x * blockDim.x + threadIdx.x;
  if (t < WT_MU) {                       // um layers: [64][128], Wl|Wr fused
    int l = t / 8192, r = t % 8192, j = r / 128, k = r % 128;
    g_wt[t] = (k < 64) ? Wl_um[l * 4096 + k * 64 + j]
                       : Wr_um[l * 4096 + (k - 64) * 64 + j];
  } else if (t < WT_JKU) {               // mu layers
    int r0 = t - WT_MU;
    int l = r0 / 8192, r = r0 % 8192, j = r / 128, k = r % 128;
    g_wt[t] = (k < 64) ? Wl_mu[l * 4096 + k * 64 + j]
                       : Wr_mu[l * 4096 + (k - 64) * 64 + j];
  } else if (t < WT_TOTAL - WT_C2 + WT_JKU) {  // classifier GEMM2: [32][64]
    int r = t - WT_JKU, j = r / 64, k = r % 64;
    g_wt[WT_C2 + r] = W2[k * 32 + j];
  }
}

// ---------------------------------------------------------------------------
// Compose JK projections with classifier W1 (linear fusion):
//   Wcu[j][a] = sum_b puW[a][b]*W1[b][j]     (192x64, wt layout at WT_JKU)
//   Wcm[j][a] = sum_b pmW[a][b]*W1[64+b][j]  (at WT_JKM)
//   cbias[j]      = b1[j] + sum_b pub[b]*W1[b][j]
//   cbias[64+j]   =         sum_b pmb[b]*W1[64+b][j]
// ---------------------------------------------------------------------------
__global__ void k_comp(const float* __restrict__ puW, const float* __restrict__ pub,
                       const float* __restrict__ pmW, const float* __restrict__ pmb,
                       const float* __restrict__ W1, const float* __restrict__ b1) {
  int t = blockIdx.x * blockDim.x + threadIdx.x;
  if (t < 12288) {
    int j = t / 192, a = t % 192;
    float s = 0.f;
#pragma unroll 8
    for (int b = 0; b < 64; b++) s += puW[a * 64 + b] * W1[b * 64 + j];
    g_wt[WT_JKU + t] = s;
  } else if (t < 24576) {
    int r = t - 12288, j = r / 192, a = r % 192;
    float s = 0.f;
#pragma unroll 8
    for (int b = 0; b < 64; b++) s += pmW[a * 64 + b] * W1[(64 + b) * 64 + j];
    g_wt[WT_JKM + r] = s;
  } else if (t < 24640) {
    int j = t - 24576;
    float s = b1[j];
    for (int b = 0; b < 64; b++) s += pub[b] * W1[b * 64 + j];
    g_cbias[j] = s;
  } else if (t < 24704) {
    int j = t - 24640;
    float s = 0.f;
    for (int b = 0; b < 64; b++) s += pmb[b] * W1[(64 + b) * 64 + j];
    g_cbias[64 + j] = s;
  }
}

// ---------------------------------------------------------------------------
// Init: gather x_u0 = user_emb[n_id], copy x_m0, zero counts + stats
// ---------------------------------------------------------------------------
__global__ void k_init(const int* __restrict__ n_id,
                       const float* __restrict__ user_emb,
                       const float* __restrict__ movie_x) {
  int t = blockIdx.x * blockDim.x + threadIdx.x;
  const int A = NU * 16, B = NM * 16, C = NU, D = NM;
  if (t < A) {
    int i = t >> 4, q = t & 15;
    ((float4*)g_xu0)[t] = ((const float4*)user_emb)[n_id[i] * 16 + q];
  } else if (t < A + B) {
    ((float4*)g_xm0)[t - A] = ((const float4*)movie_x)[t - A];
  } else if (t < A + B + C) {
    g_cntu[t - A - B] = 0;
  } else if (t < A + B + C + D) {
    g_cntm[t - A - B - C] = 0;
  } else {
    int j = t - (A + B + C + D);
    if (j < 128) g_stats1[j] = 0.f;
    else if (j < 192) g_stats2[j - 128] = 0.f;
  }
}

__global__ void k_count(const int* __restrict__ eu, const int* __restrict__ em) {
  int e = blockIdx.x * blockDim.x + threadIdx.x;
  if (e < NE) {
    atomicAdd(&g_cntu[eu[e]], 1);
    atomicAdd(&g_cntm[em[e]], 1);
  }
}

// ---------------------------------------------------------------------------
// Parallel CSR scan, 3 phases.
// ---------------------------------------------------------------------------
__global__ void k_scan_a() {
  int b = blockIdx.x;
  const int* cnt; int n, bl;
  if (b < BU) { cnt = g_cntu; n = NU; bl = b; }
  else        { cnt = g_cntm; n = NM; bl = b - BU; }
  int i0 = bl * SC + threadIdx.x * 4;
  int s = 0;
#pragma unroll
  for (int j = 0; j < 4; j++) {
    int i = i0 + j;
    if (i < n) s += cnt[i];
  }
#pragma unroll
  for (int d = 16; d >= 1; d >>= 1) s += __shfl_down_sync(0xffffffffu, s, d);
  __shared__ int sp[32];
  int wid = threadIdx.x >> 5, lane = threadIdx.x & 31;
  if (lane == 0) sp[wid] = s;
  __syncthreads();
  if (wid == 0) {
    int v = sp[lane];
#pragma unroll
    for (int d = 16; d >= 1; d >>= 1) v += __shfl_down_sync(0xffffffffu, v, d);
    if (lane == 0) g_part[b] = v;
  }
}

__global__ void k_scan_b() {
  int run = 0;
  for (int b = 0; b < BU; b++) { g_part2[b] = run; run += g_part[b]; }
  run = 0;
  for (int b = BU; b < NSB; b++) { g_part2[b] = run; run += g_part[b]; }
}

__global__ void k_scan_c() {
  int b = blockIdx.x;
  const int* cnt; int n, bl; int* offs; int* cur;
  if (b < BU) { cnt = g_cntu; n = NU; bl = b; offs = g_offu; cur = g_curu; }
  else        { cnt = g_cntm; n = NM; bl = b - BU; offs = g_offm; cur = g_curm; }
  int t = threadIdx.x;
  int i0 = bl * SC + t * 4;
  int v[4];
  int tsum = 0;
#pragma unroll
  for (int j = 0; j < 4; j++) {
    int i = i0 + j;
    v[j] = (i < n) ? cnt[i] : 0;
    tsum += v[j];
  }
  __shared__ int sp[1024];
  sp[t] = tsum;
  __syncthreads();
  for (int d = 1; d < 1024; d <<= 1) {
    int x = (t >= d) ? sp[t - d] : 0;
    __syncthreads();
    sp[t] += x;
    __syncthreads();
  }
  int p = g_part2[b] + sp[t] - tsum;
#pragma unroll
  for (int j = 0; j < 4; j++) {
    int i = i0 + j;
    if (i < n) { offs[i] = p; cur[i] = p; p += v[j]; }
  }
  if (i0 <= n - 1 && n - 1 < i0 + 4) offs[n] = p;
}

__global__ void k_fill(const int* __restrict__ eu, const int* __restrict__ em) {
  int e = blockIdx.x * blockDim.x + threadIdx.x;
  if (e < NE) {
    int u = eu[e], m = em[e];
    g_srcm[atomicAdd(&g_curm[m], 1)] = u;
    g_srcu[atomicAdd(&g_curu[u], 1)] = m;
  }
}

// ---------------------------------------------------------------------------
// Mean aggregation core: warp per dst; two half-warps, 4 neighbors in flight.
// ---------------------------------------------------------------------------
__device__ __forceinline__ void agg_core(
    int w, int lane, const int* __restrict__ offs, const int* __restrict__ src,
    const float* __restrict__ x, int ldx, float* __restrict__ agg) {
  int half = lane >> 4, li = lane & 15;
  int s0 = offs[w], s1 = offs[w + 1];
  float ax = 0.f, ay = 0.f, az = 0.f, aw = 0.f;
  int s = s0 + half;
  for (; s + 6 < s1; s += 8) {
    int ga = __ldg(src + s);
    int gb = __ldg(src + s + 2);
    int gc = __ldg(src + s + 4);
    int gd = __ldg(src + s + 6);
    float4 va = *(const float4*)(x + (size_t)ga * ldx + li * 4);
    float4 vb = *(const float4*)(x + (size_t)gb * ldx + li * 4);
    float4 vc = *(const float4*)(x + (size_t)gc * ldx + li * 4);
    float4 vd = *(const float4*)(x + (size_t)gd * ldx + li * 4);
    ax += va.x + vb.x + vc.x + vd.x;
    ay += va.y + vb.y + vc.y + vd.y;
    az += va.z + vb.z + vc.z + vd.z;
    aw += va.w + vb.w + vc.w + vd.w;
  }
  for (; s < s1; s += 2) {
    int g = __ldg(src + s);
    float4 v = *(const float4*)(x + (size_t)g * ldx + li * 4);
    ax += v.x; ay += v.y; az += v.z; aw += v.w;
  }
  ax += __shfl_xor_sync(0xffffffffu, ax, 16);
  ay += __shfl_xor_sync(0xffffffffu, ay, 16);
  az += __shfl_xor_sync(0xffffffffu, az, 16);
  aw += __shfl_xor_sync(0xffffffffu, aw, 16);
  if (half == 0) {
    float inv = 1.f / fmaxf((float)(s1 - s0), 1.f);
    *(float4*)(agg + (size_t)w * HD + li * 4) =
        make_float4(ax * inv, ay * inv, az * inv, aw * inv);
  }
}

// Dual aggregation: warps [0,nA) -> movies, [nA,nA+nB) -> users
__global__ void k_agg_dual(
    const int* __restrict__ offsA, const int* __restrict__ srcA,
    const float* __restrict__ xA, int ldA, float* __restrict__ aggA, int nA,
    const int* __restrict__ offsB, const int* __restrict__ srcB,
    const float* __restrict__ xB, int ldB, float* __restrict__ aggB, int nB) {
  int w = (blockIdx.x * blockDim.x + threadIdx.x) >> 5;
  int lane = threadIdx.x & 31;
  if (w < nA) agg_core(w, lane, offsA, srcA, xA, ldA, aggA);
  else if (w < nA + nB) agg_core(w - nA, lane, offsB, srcB, xB, ldB, aggB);
}

// ---------------------------------------------------------------------------
// Gathered-row GEMM core: 128-row x NOUT tile (64 rowpairs), 256 threads.
// ---------------------------------------------------------------------------
template <int K0, int K1, int NOUT, int MODE0, int RELU, int STATS>
__device__ __forceinline__ void gemm_core(
    int rowBase,
    const float* __restrict__ src0, int ld0, const int* __restrict__ gidx0,
    const float* __restrict__ src1, int ld1, const int* __restrict__ gidx1,
    const float* __restrict__ WT,
    const float* __restrict__ bias, const float* __restrict__ aff,
    float* __restrict__ out, int ldout, int nrows,
    float* __restrict__ stats, char* smem_raw) {
  constexpr int K = K0 + K1;
  constexpr int K4 = K / 4;
  constexpr int TN = NOUT / 16;
  constexpr int S8 = K + 2;
  constexpr size_t ASZ = (size_t)64 * S8 * 8;
  u64* sA2 = (u64*)smem_raw;
  int* sidx = (int*)(smem_raw + ASZ);

  int tid = threadIdx.x;

  if (tid < 128) {
    int row = rowBase + tid;
    sidx[tid] = (row < nrows) ? (gidx0 ? gidx0[row] : row) : -1;
  } else if (K1 > 0) {
    int r = tid - 128;
    int row = rowBase + r;
    sidx[128 + r] = (row < nrows) ? (gidx1 ? gidx1[row] : row) : -1;
  }
  __syncthreads();

  for (int it = tid; it < 64 * K4; it += 256) {
    int rp = it & 63, k4 = it >> 6;
    int k = k4 * 4;
    float4 v0 = make_float4(0.f, 0.f, 0.f, 0.f);
    float4 v1 = make_float4(0.f, 0.f, 0.f, 0.f);
    if (k < K0) {
      int ga = sidx[2 * rp], gb = sidx[2 * rp + 1];
      if (ga >= 0) v0 = *(const float4*)(src0 + (size_t)ga * ld0 + k);
      if (gb >= 0) v1 = *(const float4*)(src0 + (size_t)gb * ld0 + k);
      if constexpr (MODE0 == 1) {
        float a0 = aff[k], a1 = aff[k + 1], a2 = aff[k + 2], a3 = aff[k + 3];
        float c0 = aff[K0 + k], c1 = aff[K0 + k + 1], c2 = aff[K0 + k + 2], c3 = aff[K0 + k + 3];
        v0.x = fmaxf(a0 * v0.x + c0, 0.f); v0.y = fmaxf(a1 * v0.y + c1, 0.f);
        v0.z = fmaxf(a2 * v0.z + c2, 0.f); v0.w = fmaxf(a3 * v0.w + c3, 0.f);
        v1.x = fmaxf(a0 * v1.x + c0, 0.f); v1.y = fmaxf(a1 * v1.y + c1, 0.f);
        v1.z = fmaxf(a2 * v1.z + c2, 0.f); v1.w = fmaxf(a3 * v1.w + c3, 0.f);
      }
    } else {
      int ga = sidx[128 + 2 * rp], gb = sidx[128 + 2 * rp + 1];
      int kk = k - K0;
      if (ga >= 0) v0 = *(const float4*)(src1 + (size_t)ga * ld1 + kk);
      if (gb >= 0) v1 = *(const float4*)(src1 + (size_t)gb * ld1 + kk);
    }
    u64* dst = sA2 + (size_t)rp * S8 + k;
    *(ulonglong2*)dst = make_ulonglong2(pk2(v0.x, v1.x), pk2(v0.y, v1.y));
    *(ulonglong2*)(dst + 2) = make_ulonglong2(pk2(v0.z, v1.z), pk2(v0.w, v1.w));
  }
  __syncthreads();

  int lane = tid & 31;
  int tr = lane & 15;
  int tc = ((tid >> 5) << 1) | (lane >> 4);

  u64 acc[4][TN];
#pragma unroll
  for (int r = 0; r < 4; r++)
#pragma unroll
    for (int j = 0; j < TN; j++) acc[r][j] = 0ull;

#pragma unroll 4
  for (int k4 = 0; k4 < K4; k4++) {
    int k = k4 * 4;
    u64 a[4][4];
#pragma unroll
    for (int r = 0; r < 4; r++) {
      const ulonglong2* p = (const ulonglong2*)(sA2 + (size_t)(tr + r * 16) * S8 + k);
      ulonglong2 u = p[0];
      ulonglong2 v = p[1];
      a[r][0] = u.x; a[r][1] = u.y; a[r][2] = v.x; a[r][3] = v.y;
    }
#pragma unroll
    for (int j = 0; j < TN; j++) {
      float4 w4 = __ldg((const float4*)(WT + (size_t)(tc * TN + j) * K + k));
      u64 w0 = pkdup(w4.x), w1 = pkdup(w4.y), w2 = pkdup(w4.z), w3 = pkdup(w4.w);
#pragma unroll
      for (int r = 0; r < 4; r++) {
        ffma2(acc[r][j], a[r][0], w0);
        ffma2(acc[r][j], a[r][1], w1);
        ffma2(acc[r][j], a[r][2], w2);
        ffma2(acc[r][j], a[r][3], w3);
      }
    }
  }

  float bcol[TN];
#pragma unroll
  for (int j = 0; j < TN; j++) bcol[j] = __ldg(bias + tc * TN + j);

  float ssum[TN], ssq[TN];
  if constexpr (STATS) {
#pragma unroll
    for (int j = 0; j < TN; j++) { ssum[j] = 0.f; ssq[j] = 0.f; }
  }

#pragma unroll
  for (int r = 0; r < 4; r++) {
    int rp = tr + r * 16;
    int row0 = rowBase + 2 * rp, row1 = row0 + 1;
    float v0[TN], v1[TN];
#pragma unroll
    for (int j = 0; j < TN; j++) {
      float lo, hi;
      unpk2(acc[r][j], lo, hi);
      lo += bcol[j]; hi += bcol[j];
      if constexpr (RELU) { lo = fmaxf(lo, 0.f); hi = fmaxf(hi, 0.f); }
      v0[j] = lo; v1[j] = hi;
      if constexpr (STATS) {
        if (row0 < nrows) { ssum[j] += lo; ssq[j] += lo * lo; }
        if (row1 < nrows) { ssum[j] += hi; ssq[j] += hi * hi; }
      }
    }
    if (row0 < nrows) {
      if constexpr (TN == 4)
        *(float4*)(out + (size_t)row0 * ldout + tc * 4) = make_float4(v0[0], v0[1], v0[2], v0[3]);
      else
        *(float2*)(out + (size_t)row0 * ldout + tc * 2) = make_float2(v0[0], v0[1]);
    }
    if (row1 < nrows) {
      if constexpr (TN == 4)
        *(float4*)(out + (size_t)row1 * ldout + tc * 4) = make_float4(v1[0], v1[1], v1[2], v1[3]);
      else
        *(float2*)(out + (size_t)row1 * ldout + tc * 2) = make_float2(v1[0], v1[1]);
    }
  }

  if constexpr (STATS) {
#pragma unroll
    for (int j = 0; j < TN; j++) {
      float s = ssum[j], q = ssq[j];
#pragma unroll
      for (int d = 8; d >= 1; d >>= 1) {
        s += __shfl_down_sync(0xffffffffu, s, d, 16);
        q += __shfl_down_sync(0xffffffffu, q, d, 16);
      }
      if (tr == 0) {
        int col = tc * TN + j;
        atomicAdd(&stats[col], s);
        atomicAdd(&stats[NOUT + col], q);
      }
    }
  }
}

// Single-problem GEMM (classifier GEMM2)
template <int K0, int K1, int NOUT, int MODE0, int RELU, int STATS>
__global__ __launch_bounds__(256, 3) void k_gemm(
    const float* __restrict__ src0, int ld0, const int* __restrict__ gidx0,
    const float* __restrict__ src1, int ld1, const int* __restrict__ gidx1,
    const float* __restrict__ WT,
    const float* __restrict__ bias, const float* __restrict__ aff,
    float* __restrict__ out, int ldout, int nrows,
    float* __restrict__ stats) {
  extern __shared__ __align__(16) char smem_raw[];
  gemm_core<K0, K1, NOUT, MODE0, RELU, STATS>(
      blockIdx.x * 128, src0, ld0, gidx0, src1, ld1, gidx1, WT, bias, aff,
      out, ldout, nrows, stats, smem_raw);
}

// Dual-problem GEMM (layer movie+user pair, or composed-JK pair)
template <int K0, int K1, int NOUT, int RELU>
__global__ __launch_bounds__(256, 3) void k_gemm_dual(
    int nb0,
    const float* __restrict__ s0a, const float* __restrict__ s1a, int ld1a,
    const float* __restrict__ WTa, const float* __restrict__ biasa,
    float* __restrict__ outa, int nrowsa,
    const float* __restrict__ s0b, const float* __restrict__ s1b, int ld1b,
    const float* __restrict__ WTb, const float* __restrict__ biasb,
    float* __restrict__ outb, int nrowsb,
    int ld0, int ldout) {
  extern __shared__ __align__(16) char smem_raw[];
  if ((int)blockIdx.x < nb0)
    gemm_core<K0, K1, NOUT, 0, RELU, 0>(
        blockIdx.x * 128, s0a, ld0, nullptr, s1a, ld1a, nullptr, WTa, biasa,
        nullptr, outa, ldout, nrowsa, nullptr, smem_raw);
  else
    gemm_core<K0, K1, NOUT, 0, RELU, 0>(
        (blockIdx.x - nb0) * 128, s0b, ld0, nullptr, s1b, ld1b, nullptr, WTb,
        biasb, nullptr, outb, ldout, nrowsb, nullptr, smem_raw);
}

// ---------------------------------------------------------------------------
// Classifier stage 1 (replaces 500k-row GEMM): t1[e] = pu[lu[e]] + pm[lm[e]],
// fused BN1 stats. 16 threads per edge (one float4 chunk each).
// ---------------------------------------------------------------------------
__global__ __launch_bounds__(256) void k_gadd(const int* __restrict__ lu,
                                              const int* __restrict__ lm) {
  __shared__ float ss[128];
  int tid = threadIdx.x;
  if (tid < 128) ss[tid] = 0.f;
  __syncthreads();
  int c = tid & 15;   // chunk: columns c*4..c*4+3 (invariant under stride)
  float s0 = 0.f, s1 = 0.f, s2 = 0.f, s3 = 0.f;
  float q0 = 0.f, q1 = 0.f, q2 = 0.f, q3 = 0.f;
  int stride = gridDim.x * 256;
  for (int gid = blockIdx.x * 256 + tid; gid < NEL * 16; gid += stride) {
    int e = gid >> 4;
    int iu = __ldg(lu + e), im = __ldg(lm + e);
    float4 a = *(const float4*)(g_hu + (size_t)iu * 64 + c * 4);
    float4 b = *(const float4*)(g_hm + (size_t)im * 64 + c * 4);
    float4 r = make_float4(a.x + b.x, a.y + b.y, a.z + b.z, a.w + b.w);
    *(float4*)(g_t1 + (size_t)e * 64 + c * 4) = r;
    s0 += r.x; s1 += r.y; s2 += r.z; s3 += r.w;
    q0 += r.x * r.x; q1 += r.y * r.y; q2 += r.z * r.z; q3 += r.w * r.w;
  }
  // combine lanes c and c+16 within each warp
  s0 += __shfl_down_sync(0xffffffffu, s0, 16);
  s1 += __shfl_down_sync(0xffffffffu, s1, 16);
  s2 += __shfl_down_sync(0xffffffffu, s2, 16);
  s3 += __shfl_down_sync(0xffffffffu, s3, 16);
  q0 += __shfl_down_sync(0xffffffffu, q0, 16);
  q1 += __shfl_down_sync(0xffffffffu, q1, 16);
  q2 += __shfl_down_sync(0xffffffffu, q2, 16);
  q3 += __shfl_down_sync(0xffffffffu, q3, 16);
  if ((tid & 31) < 16) {
    atomicAdd(&ss[c * 4 + 0], s0);
    atomicAdd(&ss[c * 4 + 1], s1);
    atomicAdd(&ss[c * 4 + 2], s2);
    atomicAdd(&ss[c * 4 + 3], s3);
    atomicAdd(&ss[64 + c * 4 + 0], q0);
    atomicAdd(&ss[64 + c * 4 + 1], q1);
    atomicAdd(&ss[64 + c * 4 + 2], q2);
    atomicAdd(&ss[64 + c * 4 + 3], q3);
  }
  __syncthreads();
  if (tid < 128) atomicAdd(&g_stats1[tid], ss[tid]);
}

// BN training-mode affine: a = g*rsqrt(var+eps), c = be - mean*a
__global__ void k_bnprep(const float* __restrict__ stats, const float* __restrict__ g,
                         const float* __restrict__ be, float* __restrict__ ab,
                         int n, float invN) {
  int j = threadIdx.x;
  if (j < n) {
    float m = stats[j] * invN;
    float v = stats[n + j] * invN - m * m;
    float a = g[j] * rsqrtf(v + 1e-5f);
    ab[j] = a;
    ab[n + j] = be[j] - m * a;
  }
}

// Final: out[e] = sum_j relu(a2[j]*t2[e][j]+c2[j]) * W3[j] + b3
__global__ void k_final(const float* __restrict__ W3, const float* __restrict__ b3,
                        float* __restrict__ out) {
  __shared__ float sa[32], sc[32], sw[32];
  int tid = threadIdx.x;
  if (tid < 32) { sa[tid] = g_ab2[tid]; sc[tid] = g_ab2[32 + tid]; sw[tid] = W3[tid]; }
  __syncthreads();
  int e = blockIdx.x * blockDim.x + tid;
  if (e < NEL) {
    const float4* r = (const float4*)(g_t2 + (size_t)e * 32);
    float acc = b3[0];
#pragma unroll
    for (int q = 0; q < 8; q++) {
      float4 v = r[q];
      int k = q * 4;
      acc += fmaxf(sa[k] * v.x + sc[k], 0.f) * sw[k];
      acc += fmaxf(sa[k + 1] * v.y + sc[k + 1], 0.f) * sw[k + 1];
      acc += fmaxf(sa[k + 2] * v.z + sc[k + 2], 0.f) * sw[k + 2];
      acc += fmaxf(sa[k + 3] * v.w + sc[k + 3], 0.f) * sw[k + 3];
    }
    out[e] = acc;
  }
}

// ---------------------------------------------------------------------------
// Host launcher
// ---------------------------------------------------------------------------
static inline int cdiv(int a, int b) { return (a + b - 1) / b; }
static inline int smemsz(int K) { return 64 * (K + 2) * 8 + 1024; }

extern "C" void kernel_launch(void* const* d_in, const int* in_sizes, int n_in,
                              void* d_out, int out_size) {
  const int*   n_id    = (const int*)d_in[0];
  const float* movie_x = (const float*)d_in[1];
  const int*   eu      = (const int*)d_in[2];
  const int*   em      = (const int*)d_in[3];
  const int*   lu      = (const int*)d_in[4];
  const int*   lm      = (const int*)d_in[5];
  const float* uemb    = (const float*)d_in[6];
  const float* Wl_um   = (const float*)d_in[7];
  const float* b_um    = (const float*)d_in[8];
  const float* Wr_um   = (const float*)d_in[9];
  const float* Wl_mu   = (const float*)d_in[10];
  const float* b_mu    = (const float*)d_in[11];
  const float* Wr_mu   = (const float*)d_in[12];
  const float* puW     = (const float*)d_in[13];
  const float* pub     = (const float*)d_in[14];
  const float* pmW     = (const float*)d_in[15];
  const float* pmb     = (const float*)d_in[16];
  const float* W1      = (const float*)d_in[17];
  const float* b1      = (const float*)d_in[18];
  const float* g1      = (const float*)d_in[19];
  const float* be1     = (const float*)d_in[20];
  const float* W2      = (const float*)d_in[21];
  const float* b2      = (const float*)d_in[22];
  const float* g2      = (const float*)d_in[23];
  const float* be2     = (const float*)d_in[24];
  const float* W3      = (const float*)d_in[25];
  const float* b3      = (const float*)d_in[26];
  float* out = (float*)d_out;

  float *xu0, *xm0, *catu, *catm, *aggu, *aggm, *hu, *hm, *t1, *t2;
  float *stats1, *stats2, *ab1, *ab2, *wt, *cbias;
  int *offu, *offm, *srcu, *srcm;
  cudaGetSymbolAddress((void**)&xu0, g_xu0);
  cudaGetSymbolAddress((void**)&xm0, g_xm0);
  cudaGetSymbolAddress((void**)&catu, g_catu);
  cudaGetSymbolAddress((void**)&catm, g_catm);
  cudaGetSymbolAddress((void**)&aggu, g_aggu);
  cudaGetSymbolAddress((void**)&aggm, g_aggm);
  cudaGetSymbolAddress((void**)&hu, g_hu);
  cudaGetSymbolAddress((void**)&hm, g_hm);
  cudaGetSymbolAddress((void**)&t1, g_t1);
  cudaGetSymbolAddress((void**)&t2, g_t2);
  cudaGetSymbolAddress((void**)&stats1, g_stats1);
  cudaGetSymbolAddress((void**)&stats2, g_stats2);
  cudaGetSymbolAddress((void**)&ab1, g_ab1);
  cudaGetSymbolAddress((void**)&ab2, g_ab2);
  cudaGetSymbolAddress((void**)&offu, g_offu);
  cudaGetSymbolAddress((void**)&offm, g_offm);
  cudaGetSymbolAddress((void**)&srcu, g_srcu);
  cudaGetSymbolAddress((void**)&srcm, g_srcm);
  cudaGetSymbolAddress((void**)&wt, g_wt);
  cudaGetSymbolAddress((void**)&cbias, g_cbias);

  const int SM128 = smemsz(128);   // 67584 B -> 3 blocks/SM
  const int SM192 = smemsz(192);   // 100352 B -> 2 blocks/SM
  const int SM64  = smemsz(64);    // 34816 B
  cudaFuncSetAttribute((const void*)k_gemm<64, 0, 32, 1, 0, 1>,
                       cudaFuncAttributeMaxDynamicSharedMemorySize, SM64);
  cudaFuncSetAttribute((const void*)k_gemm_dual<64, 64, 64, 1>,
                       cudaFuncAttributeMaxDynamicSharedMemorySize, SM128);
  cudaFuncSetAttribute((const void*)k_gemm_dual<192, 0, 64, 0>,
                       cudaFuncAttributeMaxDynamicSharedMemorySize, SM192);

  // --- setup + CSR build ---
  k_wt<<<cdiv(WT_JKU + 2048, 256), 256>>>(Wl_um, Wr_um, Wl_mu, Wr_mu, W2);
  k_comp<<<cdiv(24704, 256), 256>>>(puW, pub, pmW, pmb, W1, b1);
  int initThreads = NU * 16 + NM * 16 + NU + NM + 192;
  k_init<<<cdiv(initThreads, 256), 256>>>(n_id, uemb, movie_x);
  k_count<<<cdiv(NE, 256), 256>>>(eu, em);
  k_scan_a<<<NSB, 1024>>>();
  k_scan_b<<<1, 1>>>();
  k_scan_c<<<NSB, 1024>>>();
  k_fill<<<cdiv(NE, 256), 256>>>(eu, em);

  const int NBM = cdiv(NM, 128);   // 157
  const int NBU = cdiv(NU, 128);   // 782
  const int AGG_BLOCKS = cdiv((NM + NU) * 32, 256);

  // --- 3 SAGE layers ---
  for (int l = 0; l < 3; l++) {
    const float* xu = l ? (catu + (l - 1) * 64) : xu0;
    const float* xm = l ? (catm + (l - 1) * 64) : xm0;
    int ldu = l ? 192 : 64;
    int ldm = l ? 192 : 64;

    k_agg_dual<<<AGG_BLOCKS, 256>>>(
        offm, srcm, xu, ldu, aggm, NM,
        offu, srcu, xm, ldm, aggu, NU);

    k_gemm_dual<64, 64, 64, 1><<<NBM + NBU, 256, SM128>>>(
        NBM,
        aggm, xm, ldm, wt + WT_UM + l * 8192, b_um + l * 64, catm + l * 64, NM,
        aggu, xu, ldu, wt + WT_MU + l * 8192, b_mu + l * 64, catu + l * 64, NU,
        64, 192);
  }

  // --- composed JK x W1 projections: pu/pm (fold classifier GEMM1 weights) ---
  k_gemm_dual<192, 0, 64, 0><<<NBU + NBM, 256, SM192>>>(
      NBU,
      catu, nullptr, 0, wt + WT_JKU, cbias, hu, NU,
      catm, nullptr, 0, wt + WT_JKM, cbias + 64, hm, NM,
      192, 64);

  // --- classifier stage 1: t1 = pu[lu] + pm[lm] (+ BN1 stats) ---
  k_gadd<<<1184, 256>>>(lu, lm);
  k_bnprep<<<1, 64>>>(stats1, g1, be1, ab1, 64, 1.f / NEL);

  // --- t2 = relu(bn1(t1)) @ W2 + b2 (+ BN2 stats) ---
  k_gemm<64, 0, 32, 1, 0, 1><<<cdiv(NEL, 128), 256, SM64>>>(
      t1, 64, nullptr, nullptr, 0, nullptr, wt + WT_C2,
      b2, ab1, t2, 32, NEL, stats2);
  k_bnprep<<<1, 32>>>(stats2, g2, be2, ab2, 32, 1.f / NEL);

  // --- out = relu(bn2(t2)) @ W3 + b3 ---
  k_final<<<cdiv(NEL, 256), 256>>>(W3, b3, out);
}